// round 7
// baseline (speedup 1.0000x reference)
#include <cuda_runtime.h>
#include <cuda_fp16.h>

#define N_NODES 50000
#define N_EDGES 800000
#define IN_F 256
#define HID 128
#define OUT_F 64
#define ATTN_SLOPE 0.2f
#define ACT_SLOPE 0.01f
#define NEG_BIG -1.0e30f
#define FULLMASK 0xFFFFFFFFu

typedef unsigned long long ull;

// -------- packed f32x2 helpers (Blackwell FFMA2) --------
__device__ __forceinline__ ull fma2(ull a, ull b, ull c) {
    ull d;
    asm("fma.rn.f32x2 %0, %1, %2, %3;" : "=l"(d) : "l"(a), "l"(b), "l"(c));
    return d;
}
__device__ __forceinline__ ull pack2(float v) {
    ull r;
    asm("mov.b64 %0, {%1, %1};" : "=l"(r) : "f"(v));
    return r;
}
__device__ __forceinline__ float2 unpack2(ull v) {
    float2 f;
    asm("mov.b64 {%0, %1}, %2;" : "=f"(f.x), "=f"(f.y) : "l"(v));
    return f;
}

// -------- scratch (device globals; no allocation allowed) --------
__device__ __half g_feat_h[N_NODES * HID];   // x @ W_gat, fp16 (gather path)
__device__ float g_el[N_NODES];
__device__ float g_er[N_NODES];
__device__ float g_agg[N_NODES * HID];
__device__ int   g_cnt[N_NODES];
__device__ int   g_row[N_NODES + 1];
__device__ int   g_cursor[N_NODES];
__device__ int   g_csr_src[N_EDGES];

// ================= zero the histogram =================
__global__ void init_cnt_kernel() {
    int tid = blockIdx.x * blockDim.x + threadIdx.x;
    int stride = gridDim.x * blockDim.x;
    for (int i = tid; i < N_NODES; i += stride) g_cnt[i] = 0;
}

// ================= histogram of dst =================
__global__ __launch_bounds__(256) void hist_kernel(const int* __restrict__ dst) {
    int i = blockIdx.x * blockDim.x + threadIdx.x;
    if (i < N_EDGES) atomicAdd(&g_cnt[dst[i]], 1);
}

// ================= single-block exclusive scan over 50000 counts =================
__global__ __launch_bounds__(1024) void scan_kernel() {
    __shared__ int sm[1024];
    const int CH = (N_NODES + 1023) / 1024;  // 49
    int tid = threadIdx.x;
    int base = tid * CH;
    int local[49];
    int sum = 0;
#pragma unroll
    for (int j = 0; j < CH; j++) {
        int idx = base + j;
        int c = (idx < N_NODES) ? g_cnt[idx] : 0;
        local[j] = c;
        sum += c;
    }
    sm[tid] = sum;
    __syncthreads();
    for (int off = 1; off < 1024; off <<= 1) {
        int v = sm[tid];
        if (tid >= off) v += sm[tid - off];
        __syncthreads();
        sm[tid] = v;
        __syncthreads();
    }
    int run = (tid > 0) ? sm[tid - 1] : 0;
#pragma unroll
    for (int j = 0; j < CH; j++) {
        int idx = base + j;
        if (idx < N_NODES) {
            g_row[idx] = run;
            g_cursor[idx] = run;
            run += local[j];
        }
    }
    if (tid == 1023) g_row[N_NODES] = N_EDGES;
}

// ================= scatter edges into CSR buckets =================
__global__ __launch_bounds__(256) void scatter_kernel(
    const int* __restrict__ src, const int* __restrict__ dst) {
    int i = blockIdx.x * blockDim.x + threadIdx.x;
    if (i >= N_EDGES) return;
    int d = dst[i];
    int pos = atomicAdd(&g_cursor[d], 1);
    g_csr_src[pos] = src[i];
}

// ================= GEMM1 + attn epilogue (FFMA2 core; feat fp16, el/er fp32) =================
__global__ __launch_bounds__(256) void gemm_feat_attn_kernel(
    const float* __restrict__ x, const float* __restrict__ W,
    const float* __restrict__ al, const float* __restrict__ ar) {
    __shared__ __align__(16) float As[2][8][132];
    __shared__ __align__(16) float Bs[2][8][128];
    __shared__ float red_l[16][130];
    __shared__ float red_r[16][130];
    const int m0 = blockIdx.x * 128;
    const int tid = threadIdx.x;
    const int tx = tid & 15;
    const int ty = tid >> 4;
    const int arow = tid >> 1;
    const int ac4  = tid & 1;
    const int brow = tid >> 5;
    const int bc4  = tid & 31;

    float4 a_reg, b_reg;
    {
        int gm = m0 + arow;
        a_reg = (gm < N_NODES)
            ? *reinterpret_cast<const float4*>(&x[gm * IN_F + ac4 * 4])
            : make_float4(0.f, 0.f, 0.f, 0.f);
        b_reg = *reinterpret_cast<const float4*>(&W[brow * HID + bc4 * 4]);
    }
    As[0][ac4 * 4 + 0][arow] = a_reg.x;
    As[0][ac4 * 4 + 1][arow] = a_reg.y;
    As[0][ac4 * 4 + 2][arow] = a_reg.z;
    As[0][ac4 * 4 + 3][arow] = a_reg.w;
    *reinterpret_cast<float4*>(&Bs[0][brow][bc4 * 4]) = b_reg;
    __syncthreads();

    // acc2[i2][j]: packed rows (2*i2, 2*i2+1) x col j
    ull acc2[4][8];
#pragma unroll
    for (int i2 = 0; i2 < 4; i2++)
#pragma unroll
        for (int j = 0; j < 8; j++) acc2[i2][j] = 0ull;

    int cur = 0;
    for (int t = 0; t < IN_F / 8; ++t) {
        if (t + 1 < IN_F / 8) {
            int k0 = (t + 1) * 8;
            int gm = m0 + arow;
            a_reg = (gm < N_NODES)
                ? *reinterpret_cast<const float4*>(&x[gm * IN_F + k0 + ac4 * 4])
                : make_float4(0.f, 0.f, 0.f, 0.f);
            b_reg = *reinterpret_cast<const float4*>(&W[(k0 + brow) * HID + bc4 * 4]);
        }
#pragma unroll
        for (int k = 0; k < 8; ++k) {
            __align__(16) float a[8];
            __align__(16) float b[8];
            *reinterpret_cast<float4*>(&a[0]) =
                *reinterpret_cast<const float4*>(&As[cur][k][ty * 4]);
            *reinterpret_cast<float4*>(&a[4]) =
                *reinterpret_cast<const float4*>(&As[cur][k][64 + ty * 4]);
            *reinterpret_cast<float4*>(&b[0]) =
                *reinterpret_cast<const float4*>(&Bs[cur][k][tx * 4]);
            *reinterpret_cast<float4*>(&b[4]) =
                *reinterpret_cast<const float4*>(&Bs[cur][k][64 + tx * 4]);
            const ull* a2 = reinterpret_cast<const ull*>(a);
#pragma unroll
            for (int j = 0; j < 8; j++) {
                ull bb = pack2(b[j]);
#pragma unroll
                for (int i2 = 0; i2 < 4; i2++)
                    acc2[i2][j] = fma2(a2[i2], bb, acc2[i2][j]);
            }
        }
        if (t + 1 < IN_F / 8) {
            int nxt = cur ^ 1;
            As[nxt][ac4 * 4 + 0][arow] = a_reg.x;
            As[nxt][ac4 * 4 + 1][arow] = a_reg.y;
            As[nxt][ac4 * 4 + 2][arow] = a_reg.z;
            As[nxt][ac4 * 4 + 3][arow] = a_reg.w;
            *reinterpret_cast<float4*>(&Bs[nxt][brow][bc4 * 4]) = b_reg;
            __syncthreads();
            cur = nxt;
        }
    }

    // unpack to accv[r][c] with same row mapping as before
    float accv[8][8];
#pragma unroll
    for (int i2 = 0; i2 < 4; i2++)
#pragma unroll
        for (int j = 0; j < 8; j++) {
            float2 f = unpack2(acc2[i2][j]);
            accv[2 * i2 + 0][j] = f.x;
            accv[2 * i2 + 1][j] = f.y;
        }

    float alv[8], arv[8];
    {
        float4 a0 = *reinterpret_cast<const float4*>(&al[tx * 4]);
        float4 a1 = *reinterpret_cast<const float4*>(&al[64 + tx * 4]);
        float4 r0 = *reinterpret_cast<const float4*>(&ar[tx * 4]);
        float4 r1 = *reinterpret_cast<const float4*>(&ar[64 + tx * 4]);
        alv[0] = a0.x; alv[1] = a0.y; alv[2] = a0.z; alv[3] = a0.w;
        alv[4] = a1.x; alv[5] = a1.y; alv[6] = a1.z; alv[7] = a1.w;
        arv[0] = r0.x; arv[1] = r0.y; arv[2] = r0.z; arv[3] = r0.w;
        arv[4] = r1.x; arv[5] = r1.y; arv[6] = r1.z; arv[7] = r1.w;
    }
#pragma unroll
    for (int r = 0; r < 8; r++) {
        int mloc = (r >> 2) * 64 + ty * 4 + (r & 3);
        int gm = m0 + mloc;
        float pl = 0.f, pr = 0.f;
#pragma unroll
        for (int c = 0; c < 8; c++) {
            pl += accv[r][c] * alv[c];
            pr += accv[r][c] * arv[c];
        }
        red_l[tx][mloc] = pl;
        red_r[tx][mloc] = pr;
        if (gm < N_NODES) {
            __half2 p0 = __float22half2_rn(make_float2(accv[r][0], accv[r][1]));
            __half2 p1 = __float22half2_rn(make_float2(accv[r][2], accv[r][3]));
            __half2 p2 = __float22half2_rn(make_float2(accv[r][4], accv[r][5]));
            __half2 p3 = __float22half2_rn(make_float2(accv[r][6], accv[r][7]));
            *reinterpret_cast<__half2*>(&g_feat_h[gm * HID + tx * 4])     = p0;
            *reinterpret_cast<__half2*>(&g_feat_h[gm * HID + tx * 4 + 2]) = p1;
            *reinterpret_cast<__half2*>(&g_feat_h[gm * HID + 64 + tx * 4])     = p2;
            *reinterpret_cast<__half2*>(&g_feat_h[gm * HID + 64 + tx * 4 + 2]) = p3;
        }
    }
    __syncthreads();
    if (tid < 128) {
        int gm = m0 + tid;
        float sl = 0.f, sr = 0.f;
#pragma unroll
        for (int t = 0; t < 16; t++) {
            sl += red_l[t][tid];
            sr += red_r[t][tid];
        }
        if (gm < N_NODES) {
            g_el[gm] = sl;
            g_er[gm] = sr;
        }
    }
}

// helper: fp16x4 load -> fp32 accumulate
__device__ __forceinline__ void fma_feat(float4& acc, float a, uint2 u) {
    __half2 h0 = *reinterpret_cast<__half2*>(&u.x);
    __half2 h1 = *reinterpret_cast<__half2*>(&u.y);
    float2 f0 = __half22float2(h0);
    float2 f1 = __half22float2(h1);
    acc.x += a * f0.x;
    acc.y += a * f0.y;
    acc.z += a * f1.x;
    acc.w += a * f1.y;
}

// ================= fused gather: per-node softmax + weighted aggregation (fp16 feat) =================
__global__ __launch_bounds__(256) void gat_gather_kernel() {
    int warp = (blockIdx.x * blockDim.x + threadIdx.x) >> 5;
    int lane = threadIdx.x & 31;
    if (warp >= N_NODES) return;
    int start = g_row[warp];
    int deg = g_row[warp + 1] - start;
    float4 acc = make_float4(0.f, 0.f, 0.f, 0.f);
    const uint2* feat8 = reinterpret_cast<const uint2*>(g_feat_h);
    if (deg > 0) {
        float er_d = g_er[warp];
        if (deg <= 32) {
            int sidx = 0;
            float e = NEG_BIG;
            if (lane < deg) {
                sidx = g_csr_src[start + lane];
                float v = g_el[sidx] + er_d;
                e = (v > 0.f) ? v : ATTN_SLOPE * v;
            }
            float m = e;
#pragma unroll
            for (int o = 16; o > 0; o >>= 1)
                m = fmaxf(m, __shfl_xor_sync(FULLMASK, m, o));
            float p = (lane < deg) ? __expf(e - m) : 0.f;
            float s = p;
#pragma unroll
            for (int o = 16; o > 0; o >>= 1)
                s += __shfl_xor_sync(FULLMASK, s, o);
            float alpha = p / s;
            int j = 0;
            for (; j + 4 <= deg; j += 4) {
                float a0 = __shfl_sync(FULLMASK, alpha, j);
                float a1 = __shfl_sync(FULLMASK, alpha, j + 1);
                float a2 = __shfl_sync(FULLMASK, alpha, j + 2);
                float a3 = __shfl_sync(FULLMASK, alpha, j + 3);
                int t0 = __shfl_sync(FULLMASK, sidx, j);
                int t1 = __shfl_sync(FULLMASK, sidx, j + 1);
                int t2 = __shfl_sync(FULLMASK, sidx, j + 2);
                int t3 = __shfl_sync(FULLMASK, sidx, j + 3);
                uint2 u0 = feat8[t0 * 32 + lane];
                uint2 u1 = feat8[t1 * 32 + lane];
                uint2 u2 = feat8[t2 * 32 + lane];
                uint2 u3 = feat8[t3 * 32 + lane];
                fma_feat(acc, a0, u0);
                fma_feat(acc, a1, u1);
                fma_feat(acc, a2, u2);
                fma_feat(acc, a3, u3);
            }
            for (; j < deg; j++) {
                float a0 = __shfl_sync(FULLMASK, alpha, j);
                int t0 = __shfl_sync(FULLMASK, sidx, j);
                uint2 u0 = feat8[t0 * 32 + lane];
                fma_feat(acc, a0, u0);
            }
        } else {
            int end = start + deg;
            float m = NEG_BIG, s = 0.f;
            for (int i = start + lane; i < end; i += 32) {
                int sx = g_csr_src[i];
                float v = g_el[sx] + er_d;
                float e = (v > 0.f) ? v : ATTN_SLOPE * v;
                float nm = fmaxf(m, e);
                s = s * __expf(m - nm) + __expf(e - nm);
                m = nm;
            }
#pragma unroll
            for (int o = 16; o > 0; o >>= 1) {
                float mo = __shfl_xor_sync(FULLMASK, m, o);
                float so = __shfl_xor_sync(FULLMASK, s, o);
                float nm = fmaxf(m, mo);
                s = s * __expf(m - nm) + so * __expf(mo - nm);
                m = nm;
            }
            float inv = 1.f / s;
            int i = start;
            for (; i + 1 < end; i += 2) {
                int s0 = g_csr_src[i];
                int s1 = g_csr_src[i + 1];
                float v0 = g_el[s0] + er_d;
                float v1 = g_el[s1] + er_d;
                float e0 = (v0 > 0.f) ? v0 : ATTN_SLOPE * v0;
                float e1 = (v1 > 0.f) ? v1 : ATTN_SLOPE * v1;
                float a0 = __expf(e0 - m) * inv;
                float a1 = __expf(e1 - m) * inv;
                uint2 u0 = feat8[s0 * 32 + lane];
                uint2 u1 = feat8[s1 * 32 + lane];
                fma_feat(acc, a0, u0);
                fma_feat(acc, a1, u1);
            }
            if (i < end) {
                int s0 = g_csr_src[i];
                float v0 = g_el[s0] + er_d;
                float e0 = (v0 > 0.f) ? v0 : ATTN_SLOPE * v0;
                float a0 = __expf(e0 - m) * inv;
                uint2 u0 = feat8[s0 * 32 + lane];
                fma_feat(acc, a0, u0);
            }
        }
    }
    reinterpret_cast<float4*>(g_agg)[warp * 32 + lane] = acc;
}

// ================= GEMM2: out = leaky(agg + bias) @ W_lin^T (FFMA2 core) =================
__global__ __launch_bounds__(256) void gemm_out_kernel(
    const float* __restrict__ Wl, const float* __restrict__ bias,
    float* __restrict__ out) {
    __shared__ __align__(16) float Wt[HID][66];
    __shared__ __align__(16) float At[16][136];
    const int tid = threadIdx.x;
    const int tx = tid & 15;
    const int ty = tid >> 4;
    const int r0 = blockIdx.x * 128;

    for (int i = tid; i < OUT_F * (HID / 4); i += 256) {
        int o = i >> 5;
        int k4 = i & 31;
        float4 w = *reinterpret_cast<const float4*>(&Wl[o * HID + k4 * 4]);
        Wt[k4 * 4 + 0][o] = w.x;
        Wt[k4 * 4 + 1][o] = w.y;
        Wt[k4 * 4 + 2][o] = w.z;
        Wt[k4 * 4 + 3][o] = w.w;
    }

    // acc2[i2][j]: packed rows (ty*8 + 2*i2, +1) x col (tx*4 + j)
    ull acc2[4][4];
#pragma unroll
    for (int i = 0; i < 4; i++)
#pragma unroll
        for (int j = 0; j < 4; j++) acc2[i][j] = 0ull;

    const int lrow = tid >> 2;
    const int kq = tid & 3;
    for (int c = 0; c < HID / 16; ++c) {
        int k0 = c * 16;
        __syncthreads();
        float4 bb4 = *reinterpret_cast<const float4*>(&bias[k0 + kq * 4]);
#pragma unroll
        for (int p = 0; p < 2; ++p) {
            int row = lrow + p * 64;
            int gr = r0 + row;
            float4 v = make_float4(0.f, 0.f, 0.f, 0.f);
            if (gr < N_NODES) {
                v = *reinterpret_cast<const float4*>(&g_agg[gr * HID + k0 + kq * 4]);
                v.x += bb4.x; v.y += bb4.y; v.z += bb4.z; v.w += bb4.w;
                v.x = (v.x > 0.f) ? v.x : ACT_SLOPE * v.x;
                v.y = (v.y > 0.f) ? v.y : ACT_SLOPE * v.y;
                v.z = (v.z > 0.f) ? v.z : ACT_SLOPE * v.z;
                v.w = (v.w > 0.f) ? v.w : ACT_SLOPE * v.w;
            }
            At[kq * 4 + 0][row] = v.x;
            At[kq * 4 + 1][row] = v.y;
            At[kq * 4 + 2][row] = v.z;
            At[kq * 4 + 3][row] = v.w;
        }
        __syncthreads();
#pragma unroll
        for (int k = 0; k < 16; ++k) {
            __align__(16) float a[8];
            *reinterpret_cast<float4*>(&a[0]) =
                *reinterpret_cast<const float4*>(&At[k][ty * 8]);
            *reinterpret_cast<float4*>(&a[4]) =
                *reinterpret_cast<const float4*>(&At[k][ty * 8 + 4]);
            const ull* a2 = reinterpret_cast<const ull*>(a);
            float b0 = Wt[k0 + k][tx * 4 + 0];
            float b1 = Wt[k0 + k][tx * 4 + 1];
            float b2 = Wt[k0 + k][tx * 4 + 2];
            float b3 = Wt[k0 + k][tx * 4 + 3];
            ull p0 = pack2(b0), p1 = pack2(b1), p2 = pack2(b2), p3 = pack2(b3);
#pragma unroll
            for (int i2 = 0; i2 < 4; i2++) {
                acc2[i2][0] = fma2(a2[i2], p0, acc2[i2][0]);
                acc2[i2][1] = fma2(a2[i2], p1, acc2[i2][1]);
                acc2[i2][2] = fma2(a2[i2], p2, acc2[i2][2]);
                acc2[i2][3] = fma2(a2[i2], p3, acc2[i2][3]);
            }
        }
    }
#pragma unroll
    for (int i2 = 0; i2 < 4; i2++) {
        float2 f0 = unpack2(acc2[i2][0]);
        float2 f1 = unpack2(acc2[i2][1]);
        float2 f2 = unpack2(acc2[i2][2]);
        float2 f3 = unpack2(acc2[i2][3]);
        int gr0 = r0 + ty * 8 + 2 * i2;
        int gr1 = gr0 + 1;
        if (gr0 < N_NODES)
            *reinterpret_cast<float4*>(&out[gr0 * OUT_F + tx * 4]) =
                make_float4(f0.x, f1.x, f2.x, f3.x);
        if (gr1 < N_NODES)
            *reinterpret_cast<float4*>(&out[gr1 * OUT_F + tx * 4]) =
                make_float4(f0.y, f1.y, f2.y, f3.y);
    }
}

// ================= stream/event fork-join for captured-graph overlap =================
namespace {
struct SideResources {
    cudaStream_t side;
    cudaEvent_t fork, join;
    SideResources() {
        cudaStreamCreateWithFlags(&side, cudaStreamNonBlocking);
        cudaEventCreateWithFlags(&fork, cudaEventDisableTiming);
        cudaEventCreateWithFlags(&join, cudaEventDisableTiming);
    }
};
}  // namespace

// ================= launch =================
extern "C" void kernel_launch(void* const* d_in, const int* in_sizes, int n_in,
                              void* d_out, int out_size) {
    static SideResources R;

    const float* x       = (const float*)d_in[0];
    const int*   src     = (const int*)d_in[1];
    const int*   dst     = (const int*)d_in[2];
    const float* W_gat   = (const float*)d_in[3];
    const float* attn_l  = (const float*)d_in[4];
    const float* attn_r  = (const float*)d_in[5];
    const float* bias    = (const float*)d_in[6];
    const float* W_lin   = (const float*)d_in[7];
    float* out = (float*)d_out;

    // Fork: CSR build on side stream; GEMM1+attn on main stream.
    cudaEventRecord(R.fork, 0);
    cudaStreamWaitEvent(R.side, R.fork, 0);

    init_cnt_kernel<<<64, 256, 0, R.side>>>();
    hist_kernel<<<(N_EDGES + 255) / 256, 256, 0, R.side>>>(dst);
    scan_kernel<<<1, 1024, 0, R.side>>>();
    scatter_kernel<<<(N_EDGES + 255) / 256, 256, 0, R.side>>>(src, dst);
    cudaEventRecord(R.join, R.side);

    gemm_feat_attn_kernel<<<(N_NODES + 127) / 128, 256>>>(x, W_gat, attn_l, attn_r);

    // Join: gather needs CSR (side) + feat/el/er (main).
    cudaStreamWaitEvent(0, R.join, 0);

    gat_gather_kernel<<<(N_NODES * 32 + 255) / 256, 256>>>();
    gemm_out_kernel<<<(N_NODES + 127) / 128, 256>>>(W_lin, bias, out);
}

// round 8
// speedup vs baseline: 1.1803x; 1.1803x over previous
#include <cuda_runtime.h>
#include <cuda_fp16.h>

#define N_NODES 50000
#define N_EDGES 800000
#define IN_F 256
#define HID 128
#define OUT_F 64
#define ATTN_SLOPE 0.2f
#define ACT_SLOPE 0.01f
#define NEG_BIG -1.0e30f
#define FULLMASK 0xFFFFFFFFu

typedef unsigned long long ull;

// -------- packed f32x2 helpers (GEMM2) --------
__device__ __forceinline__ ull fma2(ull a, ull b, ull c) {
    ull d;
    asm("fma.rn.f32x2 %0, %1, %2, %3;" : "=l"(d) : "l"(a), "l"(b), "l"(c));
    return d;
}
__device__ __forceinline__ ull pack2(float v) {
    ull r;
    asm("mov.b64 %0, {%1, %1};" : "=l"(r) : "f"(v));
    return r;
}
__device__ __forceinline__ float2 unpack2(ull v) {
    float2 f;
    asm("mov.b64 {%0, %1}, %2;" : "=f"(f.x), "=f"(f.y) : "l"(v));
    return f;
}

// -------- tensor core mma m16n8k16 fp16 -> fp32 --------
__device__ __forceinline__ void mma16816(float* c, const unsigned* a, const unsigned* b) {
    asm volatile(
        "mma.sync.aligned.m16n8k16.row.col.f32.f16.f16.f32 "
        "{%0,%1,%2,%3}, {%4,%5,%6,%7}, {%8,%9}, {%0,%1,%2,%3};\n"
        : "+f"(c[0]), "+f"(c[1]), "+f"(c[2]), "+f"(c[3])
        : "r"(a[0]), "r"(a[1]), "r"(a[2]), "r"(a[3]), "r"(b[0]), "r"(b[1]));
}

// -------- scratch (device globals; no allocation allowed) --------
__device__ __half g_feat_h[N_NODES * HID];
__device__ float g_el[N_NODES];
__device__ float g_er[N_NODES];
__device__ float g_agg[N_NODES * HID];
__device__ int   g_cnt[N_NODES];
__device__ int   g_row[N_NODES + 1];
__device__ int   g_cursor[N_NODES];
__device__ int   g_csr_src[N_EDGES];

// ================= zero the histogram =================
__global__ void init_cnt_kernel() {
    int tid = blockIdx.x * blockDim.x + threadIdx.x;
    int stride = gridDim.x * blockDim.x;
    for (int i = tid; i < N_NODES; i += stride) g_cnt[i] = 0;
}

// ================= histogram of dst =================
__global__ __launch_bounds__(256) void hist_kernel(const int* __restrict__ dst) {
    int i = blockIdx.x * blockDim.x + threadIdx.x;
    if (i < N_EDGES) atomicAdd(&g_cnt[dst[i]], 1);
}

// ================= single-block exclusive scan over 50000 counts =================
__global__ __launch_bounds__(1024) void scan_kernel() {
    __shared__ int sm[1024];
    const int CH = (N_NODES + 1023) / 1024;  // 49
    int tid = threadIdx.x;
    int base = tid * CH;
    int local[49];
    int sum = 0;
#pragma unroll
    for (int j = 0; j < CH; j++) {
        int idx = base + j;
        int c = (idx < N_NODES) ? g_cnt[idx] : 0;
        local[j] = c;
        sum += c;
    }
    sm[tid] = sum;
    __syncthreads();
    for (int off = 1; off < 1024; off <<= 1) {
        int v = sm[tid];
        if (tid >= off) v += sm[tid - off];
        __syncthreads();
        sm[tid] = v;
        __syncthreads();
    }
    int run = (tid > 0) ? sm[tid - 1] : 0;
#pragma unroll
    for (int j = 0; j < CH; j++) {
        int idx = base + j;
        if (idx < N_NODES) {
            g_row[idx] = run;
            g_cursor[idx] = run;
            run += local[j];
        }
    }
    if (tid == 1023) g_row[N_NODES] = N_EDGES;
}

// ================= scatter edges into CSR buckets =================
__global__ __launch_bounds__(256) void scatter_kernel(
    const int* __restrict__ src, const int* __restrict__ dst) {
    int i = blockIdx.x * blockDim.x + threadIdx.x;
    if (i >= N_EDGES) return;
    int d = dst[i];
    int pos = atomicAdd(&g_cursor[d], 1);
    g_csr_src[pos] = src[i];
}

// ================= GEMM1 (tensor core) + attn epilogue =================
// feat[128-tile] = x(f32->f16) @ W(f32->f16), fp32 accum.
// Block 128x128, 8 warps as 2(m) x 4(n): warp tile 64x32 via m16n8k16.
__global__ __launch_bounds__(256) void gemm_feat_attn_kernel(
    const float* __restrict__ x, const float* __restrict__ W,
    const float* __restrict__ al, const float* __restrict__ ar) {
    __shared__ __half As[2][128][40];   // [buf][m][k], pad 40 (20 words/row)
    __shared__ __half Bs[2][32][136];   // [buf][k][n], pad 136
    __shared__ float red_l[4][132];
    __shared__ float red_r[4][132];

    const int tid = threadIdx.x;
    const int m0 = blockIdx.x * 128;
    const int warp = tid >> 5;
    const int lane = tid & 31;
    const int wm = (warp & 1) * 64;
    const int wn = (warp >> 1) * 32;
    const int g = lane >> 2;   // 0..7
    const int q = lane & 3;    // 0..3

    const int arow = tid >> 1;          // 0..127
    const int akb = (tid & 1) * 16;
    const int bkr = tid >> 3;           // 0..31
    const int bnb = (tid & 7) * 16;

    float4 ax[4], bw[4];

    auto ldg_chunk = [&](int k0) {
        int gm = m0 + arow;
        if (gm < N_NODES) {
#pragma unroll
            for (int i = 0; i < 4; i++)
                ax[i] = *reinterpret_cast<const float4*>(&x[gm * IN_F + k0 + akb + 4 * i]);
        } else {
#pragma unroll
            for (int i = 0; i < 4; i++) ax[i] = make_float4(0.f, 0.f, 0.f, 0.f);
        }
#pragma unroll
        for (int i = 0; i < 4; i++)
            bw[i] = *reinterpret_cast<const float4*>(&W[(k0 + bkr) * HID + bnb + 4 * i]);
    };
    auto sts_chunk = [&](int buf) {
#pragma unroll
        for (int i = 0; i < 4; i++) {
            __half2* p = reinterpret_cast<__half2*>(&As[buf][arow][akb + 4 * i]);
            p[0] = __floats2half2_rn(ax[i].x, ax[i].y);
            p[1] = __floats2half2_rn(ax[i].z, ax[i].w);
        }
#pragma unroll
        for (int i = 0; i < 4; i++) {
            __half2* p = reinterpret_cast<__half2*>(&Bs[buf][bkr][bnb + 4 * i]);
            p[0] = __floats2half2_rn(bw[i].x, bw[i].y);
            p[1] = __floats2half2_rn(bw[i].z, bw[i].w);
        }
    };

    float acc[4][4][4];
#pragma unroll
    for (int mt = 0; mt < 4; mt++)
#pragma unroll
        for (int nt = 0; nt < 4; nt++)
#pragma unroll
            for (int c = 0; c < 4; c++) acc[mt][nt][c] = 0.f;

    ldg_chunk(0);
    sts_chunk(0);
    __syncthreads();
    int buf = 0;
    for (int ch = 0; ch < IN_F / 32; ++ch) {
        if (ch < IN_F / 32 - 1) ldg_chunk((ch + 1) * 32);
#pragma unroll
        for (int k16 = 0; k16 < 32; k16 += 16) {
            unsigned ra[4][4];
#pragma unroll
            for (int mt = 0; mt < 4; mt++) {
                int r = wm + mt * 16 + g;
                ra[mt][0] = *reinterpret_cast<const unsigned*>(&As[buf][r][k16 + q * 2]);
                ra[mt][1] = *reinterpret_cast<const unsigned*>(&As[buf][r + 8][k16 + q * 2]);
                ra[mt][2] = *reinterpret_cast<const unsigned*>(&As[buf][r][k16 + q * 2 + 8]);
                ra[mt][3] = *reinterpret_cast<const unsigned*>(&As[buf][r + 8][k16 + q * 2 + 8]);
            }
            unsigned rb[4][2];
#pragma unroll
            for (int nt = 0; nt < 4; nt++) {
                int n = wn + nt * 8 + g;
                int k = k16 + q * 2;
                __half2 h0 = __halves2half2(Bs[buf][k][n], Bs[buf][k + 1][n]);
                __half2 h1 = __halves2half2(Bs[buf][k + 8][n], Bs[buf][k + 9][n]);
                rb[nt][0] = *reinterpret_cast<unsigned*>(&h0);
                rb[nt][1] = *reinterpret_cast<unsigned*>(&h1);
            }
#pragma unroll
            for (int mt = 0; mt < 4; mt++)
#pragma unroll
                for (int nt = 0; nt < 4; nt++)
                    mma16816(acc[mt][nt], ra[mt], rb[nt]);
        }
        if (ch < IN_F / 32 - 1) {
            sts_chunk(buf ^ 1);
            __syncthreads();
            buf ^= 1;
        }
    }

    // ---- epilogue: feat (fp16) + el/er partial dots ----
    float alv[4][2], arv[4][2];
#pragma unroll
    for (int nt = 0; nt < 4; nt++) {
        int col = wn + nt * 8 + q * 2;
        alv[nt][0] = al[col];
        alv[nt][1] = al[col + 1];
        arv[nt][0] = ar[col];
        arv[nt][1] = ar[col + 1];
    }
#pragma unroll
    for (int mt = 0; mt < 4; mt++) {
        float pl0 = 0.f, pl1 = 0.f, pr0 = 0.f, pr1 = 0.f;
#pragma unroll
        for (int nt = 0; nt < 4; nt++) {
            pl0 += acc[mt][nt][0] * alv[nt][0] + acc[mt][nt][1] * alv[nt][1];
            pl1 += acc[mt][nt][2] * alv[nt][0] + acc[mt][nt][3] * alv[nt][1];
            pr0 += acc[mt][nt][0] * arv[nt][0] + acc[mt][nt][1] * arv[nt][1];
            pr1 += acc[mt][nt][2] * arv[nt][0] + acc[mt][nt][3] * arv[nt][1];
            // store feat fp16
            int row = m0 + wm + mt * 16 + g;
            int col = wn + nt * 8 + q * 2;
            if (row < N_NODES) {
                __half2 h = __floats2half2_rn(acc[mt][nt][0], acc[mt][nt][1]);
                *reinterpret_cast<__half2*>(&g_feat_h[row * HID + col]) = h;
            }
            if (row + 8 < N_NODES) {
                __half2 h = __floats2half2_rn(acc[mt][nt][2], acc[mt][nt][3]);
                *reinterpret_cast<__half2*>(&g_feat_h[(row + 8) * HID + col]) = h;
            }
        }
        // quad reduce across q (lanes 4g..4g+3)
        pl0 += __shfl_xor_sync(FULLMASK, pl0, 1);
        pl0 += __shfl_xor_sync(FULLMASK, pl0, 2);
        pl1 += __shfl_xor_sync(FULLMASK, pl1, 1);
        pl1 += __shfl_xor_sync(FULLMASK, pl1, 2);
        pr0 += __shfl_xor_sync(FULLMASK, pr0, 1);
        pr0 += __shfl_xor_sync(FULLMASK, pr0, 2);
        pr1 += __shfl_xor_sync(FULLMASK, pr1, 1);
        pr1 += __shfl_xor_sync(FULLMASK, pr1, 2);
        if (q == 0) {
            int wnidx = warp >> 1;
            red_l[wnidx][wm + mt * 16 + g] = pl0;
            red_l[wnidx][wm + mt * 16 + g + 8] = pl1;
            red_r[wnidx][wm + mt * 16 + g] = pr0;
            red_r[wnidx][wm + mt * 16 + g + 8] = pr1;
        }
    }
    __syncthreads();
    if (tid < 128) {
        int gm = m0 + tid;
        if (gm < N_NODES) {
            g_el[gm] = red_l[0][tid] + red_l[1][tid] + red_l[2][tid] + red_l[3][tid];
            g_er[gm] = red_r[0][tid] + red_r[1][tid] + red_r[2][tid] + red_r[3][tid];
        }
    }
}

// helper: fp16x4 load -> fp32 accumulate
__device__ __forceinline__ void fma_feat(float4& acc, float a, uint2 u) {
    __half2 h0 = *reinterpret_cast<__half2*>(&u.x);
    __half2 h1 = *reinterpret_cast<__half2*>(&u.y);
    float2 f0 = __half22float2(h0);
    float2 f1 = __half22float2(h1);
    acc.x += a * f0.x;
    acc.y += a * f0.y;
    acc.z += a * f1.x;
    acc.w += a * f1.y;
}

// ================= fused gather: per-node softmax + weighted aggregation (fp16 feat) =================
__global__ __launch_bounds__(256) void gat_gather_kernel() {
    int warp = (blockIdx.x * blockDim.x + threadIdx.x) >> 5;
    int lane = threadIdx.x & 31;
    if (warp >= N_NODES) return;
    int start = g_row[warp];
    int deg = g_row[warp + 1] - start;
    float4 acc = make_float4(0.f, 0.f, 0.f, 0.f);
    const uint2* feat8 = reinterpret_cast<const uint2*>(g_feat_h);
    if (deg > 0) {
        float er_d = g_er[warp];
        if (deg <= 32) {
            int sidx = 0;
            float e = NEG_BIG;
            if (lane < deg) {
                sidx = g_csr_src[start + lane];
                float v = g_el[sidx] + er_d;
                e = (v > 0.f) ? v : ATTN_SLOPE * v;
            }
            float m = e;
#pragma unroll
            for (int o = 16; o > 0; o >>= 1)
                m = fmaxf(m, __shfl_xor_sync(FULLMASK, m, o));
            float p = (lane < deg) ? __expf(e - m) : 0.f;
            float s = p;
#pragma unroll
            for (int o = 16; o > 0; o >>= 1)
                s += __shfl_xor_sync(FULLMASK, s, o);
            float alpha = p / s;
            int j = 0;
            for (; j + 4 <= deg; j += 4) {
                float a0 = __shfl_sync(FULLMASK, alpha, j);
                float a1 = __shfl_sync(FULLMASK, alpha, j + 1);
                float a2 = __shfl_sync(FULLMASK, alpha, j + 2);
                float a3 = __shfl_sync(FULLMASK, alpha, j + 3);
                int t0 = __shfl_sync(FULLMASK, sidx, j);
                int t1 = __shfl_sync(FULLMASK, sidx, j + 1);
                int t2 = __shfl_sync(FULLMASK, sidx, j + 2);
                int t3 = __shfl_sync(FULLMASK, sidx, j + 3);
                uint2 u0 = feat8[t0 * 32 + lane];
                uint2 u1 = feat8[t1 * 32 + lane];
                uint2 u2 = feat8[t2 * 32 + lane];
                uint2 u3 = feat8[t3 * 32 + lane];
                fma_feat(acc, a0, u0);
                fma_feat(acc, a1, u1);
                fma_feat(acc, a2, u2);
                fma_feat(acc, a3, u3);
            }
            for (; j < deg; j++) {
                float a0 = __shfl_sync(FULLMASK, alpha, j);
                int t0 = __shfl_sync(FULLMASK, sidx, j);
                uint2 u0 = feat8[t0 * 32 + lane];
                fma_feat(acc, a0, u0);
            }
        } else {
            int end = start + deg;
            float m = NEG_BIG, s = 0.f;
            for (int i = start + lane; i < end; i += 32) {
                int sx = g_csr_src[i];
                float v = g_el[sx] + er_d;
                float e = (v > 0.f) ? v : ATTN_SLOPE * v;
                float nm = fmaxf(m, e);
                s = s * __expf(m - nm) + __expf(e - nm);
                m = nm;
            }
#pragma unroll
            for (int o = 16; o > 0; o >>= 1) {
                float mo = __shfl_xor_sync(FULLMASK, m, o);
                float so = __shfl_xor_sync(FULLMASK, s, o);
                float nm = fmaxf(m, mo);
                s = s * __expf(m - nm) + so * __expf(mo - nm);
                m = nm;
            }
            float inv = 1.f / s;
            int i = start;
            for (; i + 1 < end; i += 2) {
                int s0 = g_csr_src[i];
                int s1 = g_csr_src[i + 1];
                float v0 = g_el[s0] + er_d;
                float v1 = g_el[s1] + er_d;
                float e0 = (v0 > 0.f) ? v0 : ATTN_SLOPE * v0;
                float e1 = (v1 > 0.f) ? v1 : ATTN_SLOPE * v1;
                float a0 = __expf(e0 - m) * inv;
                float a1 = __expf(e1 - m) * inv;
                uint2 u0 = feat8[s0 * 32 + lane];
                uint2 u1 = feat8[s1 * 32 + lane];
                fma_feat(acc, a0, u0);
                fma_feat(acc, a1, u1);
            }
            if (i < end) {
                int s0 = g_csr_src[i];
                float v0 = g_el[s0] + er_d;
                float e0 = (v0 > 0.f) ? v0 : ATTN_SLOPE * v0;
                float a0 = __expf(e0 - m) * inv;
                uint2 u0 = feat8[s0 * 32 + lane];
                fma_feat(acc, a0, u0);
            }
        }
    }
    reinterpret_cast<float4*>(g_agg)[warp * 32 + lane] = acc;
}

// ================= GEMM2: out = leaky(agg + bias) @ W_lin^T (FFMA2 core) =================
__global__ __launch_bounds__(256) void gemm_out_kernel(
    const float* __restrict__ Wl, const float* __restrict__ bias,
    float* __restrict__ out) {
    __shared__ __align__(16) float Wt[HID][66];
    __shared__ __align__(16) float At[16][136];
    const int tid = threadIdx.x;
    const int tx = tid & 15;
    const int ty = tid >> 4;
    const int r0 = blockIdx.x * 128;

    for (int i = tid; i < OUT_F * (HID / 4); i += 256) {
        int o = i >> 5;
        int k4 = i & 31;
        float4 w = *reinterpret_cast<const float4*>(&Wl[o * HID + k4 * 4]);
        Wt[k4 * 4 + 0][o] = w.x;
        Wt[k4 * 4 + 1][o] = w.y;
        Wt[k4 * 4 + 2][o] = w.z;
        Wt[k4 * 4 + 3][o] = w.w;
    }

    ull acc2[4][4];
#pragma unroll
    for (int i = 0; i < 4; i++)
#pragma unroll
        for (int j = 0; j < 4; j++) acc2[i][j] = 0ull;

    const int lrow = tid >> 2;
    const int kq = tid & 3;
    for (int c = 0; c < HID / 16; ++c) {
        int k0 = c * 16;
        __syncthreads();
        float4 bb4 = *reinterpret_cast<const float4*>(&bias[k0 + kq * 4]);
#pragma unroll
        for (int p = 0; p < 2; ++p) {
            int row = lrow + p * 64;
            int gr = r0 + row;
            float4 v = make_float4(0.f, 0.f, 0.f, 0.f);
            if (gr < N_NODES) {
                v = *reinterpret_cast<const float4*>(&g_agg[gr * HID + k0 + kq * 4]);
                v.x += bb4.x; v.y += bb4.y; v.z += bb4.z; v.w += bb4.w;
                v.x = (v.x > 0.f) ? v.x : ACT_SLOPE * v.x;
                v.y = (v.y > 0.f) ? v.y : ACT_SLOPE * v.y;
                v.z = (v.z > 0.f) ? v.z : ACT_SLOPE * v.z;
                v.w = (v.w > 0.f) ? v.w : ACT_SLOPE * v.w;
            }
            At[kq * 4 + 0][row] = v.x;
            At[kq * 4 + 1][row] = v.y;
            At[kq * 4 + 2][row] = v.z;
            At[kq * 4 + 3][row] = v.w;
        }
        __syncthreads();
#pragma unroll
        for (int k = 0; k < 16; ++k) {
            __align__(16) float a[8];
            *reinterpret_cast<float4*>(&a[0]) =
                *reinterpret_cast<const float4*>(&At[k][ty * 8]);
            *reinterpret_cast<float4*>(&a[4]) =
                *reinterpret_cast<const float4*>(&At[k][ty * 8 + 4]);
            const ull* a2 = reinterpret_cast<const ull*>(a);
            float b0 = Wt[k0 + k][tx * 4 + 0];
            float b1 = Wt[k0 + k][tx * 4 + 1];
            float b2 = Wt[k0 + k][tx * 4 + 2];
            float b3 = Wt[k0 + k][tx * 4 + 3];
            ull p0 = pack2(b0), p1 = pack2(b1), p2 = pack2(b2), p3 = pack2(b3);
#pragma unroll
            for (int i2 = 0; i2 < 4; i2++) {
                acc2[i2][0] = fma2(a2[i2], p0, acc2[i2][0]);
                acc2[i2][1] = fma2(a2[i2], p1, acc2[i2][1]);
                acc2[i2][2] = fma2(a2[i2], p2, acc2[i2][2]);
                acc2[i2][3] = fma2(a2[i2], p3, acc2[i2][3]);
            }
        }
    }
#pragma unroll
    for (int i2 = 0; i2 < 4; i2++) {
        float2 f0 = unpack2(acc2[i2][0]);
        float2 f1 = unpack2(acc2[i2][1]);
        float2 f2 = unpack2(acc2[i2][2]);
        float2 f3 = unpack2(acc2[i2][3]);
        int gr0 = r0 + ty * 8 + 2 * i2;
        int gr1 = gr0 + 1;
        if (gr0 < N_NODES)
            *reinterpret_cast<float4*>(&out[gr0 * OUT_F + tx * 4]) =
                make_float4(f0.x, f1.x, f2.x, f3.x);
        if (gr1 < N_NODES)
            *reinterpret_cast<float4*>(&out[gr1 * OUT_F + tx * 4]) =
                make_float4(f0.y, f1.y, f2.y, f3.y);
    }
}

// ================= stream/event fork-join for captured-graph overlap =================
namespace {
struct SideResources {
    cudaStream_t side;
    cudaEvent_t fork, join;
    SideResources() {
        cudaStreamCreateWithFlags(&side, cudaStreamNonBlocking);
        cudaEventCreateWithFlags(&fork, cudaEventDisableTiming);
        cudaEventCreateWithFlags(&join, cudaEventDisableTiming);
    }
};
}  // namespace

// ================= launch =================
extern "C" void kernel_launch(void* const* d_in, const int* in_sizes, int n_in,
                              void* d_out, int out_size) {
    static SideResources R;

    const float* x       = (const float*)d_in[0];
    const int*   src     = (const int*)d_in[1];
    const int*   dst     = (const int*)d_in[2];
    const float* W_gat   = (const float*)d_in[3];
    const float* attn_l  = (const float*)d_in[4];
    const float* attn_r  = (const float*)d_in[5];
    const float* bias    = (const float*)d_in[6];
    const float* W_lin   = (const float*)d_in[7];
    float* out = (float*)d_out;

    // Fork: CSR build on side stream; GEMM1+attn (tensor core) on main stream.
    cudaEventRecord(R.fork, 0);
    cudaStreamWaitEvent(R.side, R.fork, 0);

    init_cnt_kernel<<<64, 256, 0, R.side>>>();
    hist_kernel<<<(N_EDGES + 255) / 256, 256, 0, R.side>>>(dst);
    scan_kernel<<<1, 1024, 0, R.side>>>();
    scatter_kernel<<<(N_EDGES + 255) / 256, 256, 0, R.side>>>(src, dst);
    cudaEventRecord(R.join, R.side);

    gemm_feat_attn_kernel<<<(N_NODES + 127) / 128, 256>>>(x, W_gat, attn_l, attn_r);

    // Join: gather needs CSR (side) + feat/el/er (main).
    cudaStreamWaitEvent(0, R.join, 0);

    gat_gather_kernel<<<(N_NODES * 32 + 255) / 256, 256>>>();
    gemm_out_kernel<<<(N_NODES + 127) / 128, 256>>>(W_lin, bias, out);
}

// round 9
// speedup vs baseline: 1.6263x; 1.3778x over previous
#include <cuda_runtime.h>
#include <cuda_fp16.h>

#define N_NODES 50000
#define N_EDGES 800000
#define IN_F 256
#define HID 128
#define OUT_F 64
#define ATTN_SLOPE 0.2f
#define ACT_SLOPE 0.01f
#define NEG_BIG -1.0e30f
#define FULLMASK 0xFFFFFFFFu

// -------- tensor core mma m16n8k16 fp16 -> fp32 --------
__device__ __forceinline__ void mma16816(float* c, const unsigned* a, const unsigned* b) {
    asm volatile(
        "mma.sync.aligned.m16n8k16.row.col.f32.f16.f16.f32 "
        "{%0,%1,%2,%3}, {%4,%5,%6,%7}, {%8,%9}, {%0,%1,%2,%3};\n"
        : "+f"(c[0]), "+f"(c[1]), "+f"(c[2]), "+f"(c[3])
        : "r"(a[0]), "r"(a[1]), "r"(a[2]), "r"(a[3]), "r"(b[0]), "r"(b[1]));
}

// -------- scratch (device globals; no allocation allowed) --------
__device__ __half g_feat_h[N_NODES * HID];   // x @ W_gat (fp16, gather input)
__device__ __half g_act_h[N_NODES * HID];    // leaky(agg + bias) (fp16, GEMM2 input)
__device__ float g_el[N_NODES];
__device__ float g_er[N_NODES];
__device__ int   g_cnt[N_NODES];
__device__ int   g_row[N_NODES + 1];
__device__ int   g_e_ord[N_EDGES];           // per-edge ordinal within dst bucket
__device__ int   g_csr_src[N_EDGES];

// ================= zero the histogram =================
__global__ void init_cnt_kernel() {
    int tid = blockIdx.x * blockDim.x + threadIdx.x;
    int stride = gridDim.x * blockDim.x;
    for (int i = tid; i < N_NODES; i += stride) g_cnt[i] = 0;
}

// ================= histogram of dst + record ordinal =================
__global__ __launch_bounds__(256) void hist_kernel(const int* __restrict__ dst) {
    int i = blockIdx.x * blockDim.x + threadIdx.x;
    if (i < N_EDGES) g_e_ord[i] = atomicAdd(&g_cnt[dst[i]], 1);
}

// ================= single-block exclusive scan over 50000 counts =================
__global__ __launch_bounds__(1024) void scan_kernel() {
    __shared__ int sm[1024];
    const int CH = (N_NODES + 1023) / 1024;  // 49
    int tid = threadIdx.x;
    int base = tid * CH;
    int local[49];
    int sum = 0;
#pragma unroll
    for (int j = 0; j < CH; j++) {
        int idx = base + j;
        int c = (idx < N_NODES) ? g_cnt[idx] : 0;
        local[j] = c;
        sum += c;
    }
    sm[tid] = sum;
    __syncthreads();
    for (int off = 1; off < 1024; off <<= 1) {
        int v = sm[tid];
        if (tid >= off) v += sm[tid - off];
        __syncthreads();
        sm[tid] = v;
        __syncthreads();
    }
    int run = (tid > 0) ? sm[tid - 1] : 0;
#pragma unroll
    for (int j = 0; j < CH; j++) {
        int idx = base + j;
        if (idx < N_NODES) {
            g_row[idx] = run;
            run += local[j];
        }
    }
    if (tid == 1023) g_row[N_NODES] = N_EDGES;
}

// ================= place edges into CSR buckets (no atomics) =================
__global__ __launch_bounds__(256) void place_kernel(
    const int* __restrict__ src, const int* __restrict__ dst) {
    int i = blockIdx.x * blockDim.x + threadIdx.x;
    if (i >= N_EDGES) return;
    int d = dst[i];
    g_csr_src[g_row[d] + g_e_ord[i]] = src[i];
}

// ================= GEMM1 (tensor core) + attn epilogue =================
__global__ __launch_bounds__(256) void gemm_feat_attn_kernel(
    const float* __restrict__ x, const float* __restrict__ W,
    const float* __restrict__ al, const float* __restrict__ ar) {
    __shared__ __half As[2][128][40];
    __shared__ __half Bs[2][32][136];
    __shared__ float red_l[4][132];
    __shared__ float red_r[4][132];

    const int tid = threadIdx.x;
    const int m0 = blockIdx.x * 128;
    const int warp = tid >> 5;
    const int lane = tid & 31;
    const int wm = (warp & 1) * 64;
    const int wn = (warp >> 1) * 32;
    const int g = lane >> 2;
    const int q = lane & 3;

    const int arow = tid >> 1;
    const int akb = (tid & 1) * 16;
    const int bkr = tid >> 3;
    const int bnb = (tid & 7) * 16;

    float4 ax[4], bw[4];

    auto ldg_chunk = [&](int k0) {
        int gm = m0 + arow;
        if (gm < N_NODES) {
#pragma unroll
            for (int i = 0; i < 4; i++)
                ax[i] = *reinterpret_cast<const float4*>(&x[gm * IN_F + k0 + akb + 4 * i]);
        } else {
#pragma unroll
            for (int i = 0; i < 4; i++) ax[i] = make_float4(0.f, 0.f, 0.f, 0.f);
        }
#pragma unroll
        for (int i = 0; i < 4; i++)
            bw[i] = *reinterpret_cast<const float4*>(&W[(k0 + bkr) * HID + bnb + 4 * i]);
    };
    auto sts_chunk = [&](int buf) {
#pragma unroll
        for (int i = 0; i < 4; i++) {
            __half2* p = reinterpret_cast<__half2*>(&As[buf][arow][akb + 4 * i]);
            p[0] = __floats2half2_rn(ax[i].x, ax[i].y);
            p[1] = __floats2half2_rn(ax[i].z, ax[i].w);
        }
#pragma unroll
        for (int i = 0; i < 4; i++) {
            __half2* p = reinterpret_cast<__half2*>(&Bs[buf][bkr][bnb + 4 * i]);
            p[0] = __floats2half2_rn(bw[i].x, bw[i].y);
            p[1] = __floats2half2_rn(bw[i].z, bw[i].w);
        }
    };

    float acc[4][4][4];
#pragma unroll
    for (int mt = 0; mt < 4; mt++)
#pragma unroll
        for (int nt = 0; nt < 4; nt++)
#pragma unroll
            for (int c = 0; c < 4; c++) acc[mt][nt][c] = 0.f;

    ldg_chunk(0);
    sts_chunk(0);
    __syncthreads();
    int buf = 0;
    for (int ch = 0; ch < IN_F / 32; ++ch) {
        if (ch < IN_F / 32 - 1) ldg_chunk((ch + 1) * 32);
#pragma unroll
        for (int k16 = 0; k16 < 32; k16 += 16) {
            unsigned ra[4][4];
#pragma unroll
            for (int mt = 0; mt < 4; mt++) {
                int r = wm + mt * 16 + g;
                ra[mt][0] = *reinterpret_cast<const unsigned*>(&As[buf][r][k16 + q * 2]);
                ra[mt][1] = *reinterpret_cast<const unsigned*>(&As[buf][r + 8][k16 + q * 2]);
                ra[mt][2] = *reinterpret_cast<const unsigned*>(&As[buf][r][k16 + q * 2 + 8]);
                ra[mt][3] = *reinterpret_cast<const unsigned*>(&As[buf][r + 8][k16 + q * 2 + 8]);
            }
            unsigned rb[4][2];
#pragma unroll
            for (int nt = 0; nt < 4; nt++) {
                int n = wn + nt * 8 + g;
                int k = k16 + q * 2;
                __half2 h0 = __halves2half2(Bs[buf][k][n], Bs[buf][k + 1][n]);
                __half2 h1 = __halves2half2(Bs[buf][k + 8][n], Bs[buf][k + 9][n]);
                rb[nt][0] = *reinterpret_cast<unsigned*>(&h0);
                rb[nt][1] = *reinterpret_cast<unsigned*>(&h1);
            }
#pragma unroll
            for (int mt = 0; mt < 4; mt++)
#pragma unroll
                for (int nt = 0; nt < 4; nt++)
                    mma16816(acc[mt][nt], ra[mt], rb[nt]);
        }
        if (ch < IN_F / 32 - 1) {
            sts_chunk(buf ^ 1);
            __syncthreads();
            buf ^= 1;
        }
    }

    float alv[4][2], arv[4][2];
#pragma unroll
    for (int nt = 0; nt < 4; nt++) {
        int col = wn + nt * 8 + q * 2;
        alv[nt][0] = al[col];
        alv[nt][1] = al[col + 1];
        arv[nt][0] = ar[col];
        arv[nt][1] = ar[col + 1];
    }
#pragma unroll
    for (int mt = 0; mt < 4; mt++) {
        float pl0 = 0.f, pl1 = 0.f, pr0 = 0.f, pr1 = 0.f;
#pragma unroll
        for (int nt = 0; nt < 4; nt++) {
            pl0 += acc[mt][nt][0] * alv[nt][0] + acc[mt][nt][1] * alv[nt][1];
            pl1 += acc[mt][nt][2] * alv[nt][0] + acc[mt][nt][3] * alv[nt][1];
            pr0 += acc[mt][nt][0] * arv[nt][0] + acc[mt][nt][1] * arv[nt][1];
            pr1 += acc[mt][nt][2] * arv[nt][0] + acc[mt][nt][3] * arv[nt][1];
            int row = m0 + wm + mt * 16 + g;
            int col = wn + nt * 8 + q * 2;
            if (row < N_NODES) {
                __half2 h = __floats2half2_rn(acc[mt][nt][0], acc[mt][nt][1]);
                *reinterpret_cast<__half2*>(&g_feat_h[row * HID + col]) = h;
            }
            if (row + 8 < N_NODES) {
                __half2 h = __floats2half2_rn(acc[mt][nt][2], acc[mt][nt][3]);
                *reinterpret_cast<__half2*>(&g_feat_h[(row + 8) * HID + col]) = h;
            }
        }
        pl0 += __shfl_xor_sync(FULLMASK, pl0, 1);
        pl0 += __shfl_xor_sync(FULLMASK, pl0, 2);
        pl1 += __shfl_xor_sync(FULLMASK, pl1, 1);
        pl1 += __shfl_xor_sync(FULLMASK, pl1, 2);
        pr0 += __shfl_xor_sync(FULLMASK, pr0, 1);
        pr0 += __shfl_xor_sync(FULLMASK, pr0, 2);
        pr1 += __shfl_xor_sync(FULLMASK, pr1, 1);
        pr1 += __shfl_xor_sync(FULLMASK, pr1, 2);
        if (q == 0) {
            int wnidx = warp >> 1;
            red_l[wnidx][wm + mt * 16 + g] = pl0;
            red_l[wnidx][wm + mt * 16 + g + 8] = pl1;
            red_r[wnidx][wm + mt * 16 + g] = pr0;
            red_r[wnidx][wm + mt * 16 + g + 8] = pr1;
        }
    }
    __syncthreads();
    if (tid < 128) {
        int gm = m0 + tid;
        if (gm < N_NODES) {
            g_el[gm] = red_l[0][tid] + red_l[1][tid] + red_l[2][tid] + red_l[3][tid];
            g_er[gm] = red_r[0][tid] + red_r[1][tid] + red_r[2][tid] + red_r[3][tid];
        }
    }
}

// helper: fp16x4 load -> fp32 accumulate
__device__ __forceinline__ void fma_feat(float4& acc, float a, uint2 u) {
    __half2 h0 = *reinterpret_cast<__half2*>(&u.x);
    __half2 h1 = *reinterpret_cast<__half2*>(&u.y);
    float2 f0 = __half22float2(h0);
    float2 f1 = __half22float2(h1);
    acc.x += a * f0.x;
    acc.y += a * f0.y;
    acc.z += a * f1.x;
    acc.w += a * f1.y;
}

// ================= fused gather: softmax + aggregation + bias + leaky -> fp16 act =================
__global__ __launch_bounds__(256) void gat_gather_kernel(const float* __restrict__ bias) {
    int warp = (blockIdx.x * blockDim.x + threadIdx.x) >> 5;
    int lane = threadIdx.x & 31;
    if (warp >= N_NODES) return;
    int start = g_row[warp];
    int deg = g_row[warp + 1] - start;
    float4 acc = make_float4(0.f, 0.f, 0.f, 0.f);
    const uint2* feat8 = reinterpret_cast<const uint2*>(g_feat_h);
    if (deg > 0) {
        float er_d = g_er[warp];
        if (deg <= 32) {
            int sidx = 0;
            float e = NEG_BIG;
            if (lane < deg) {
                sidx = g_csr_src[start + lane];
                float v = g_el[sidx] + er_d;
                e = (v > 0.f) ? v : ATTN_SLOPE * v;
            }
            float m = e;
#pragma unroll
            for (int o = 16; o > 0; o >>= 1)
                m = fmaxf(m, __shfl_xor_sync(FULLMASK, m, o));
            float p = (lane < deg) ? __expf(e - m) : 0.f;
            float s = p;
#pragma unroll
            for (int o = 16; o > 0; o >>= 1)
                s += __shfl_xor_sync(FULLMASK, s, o);
            float alpha = p / s;
            int j = 0;
            for (; j + 4 <= deg; j += 4) {
                float a0 = __shfl_sync(FULLMASK, alpha, j);
                float a1 = __shfl_sync(FULLMASK, alpha, j + 1);
                float a2 = __shfl_sync(FULLMASK, alpha, j + 2);
                float a3 = __shfl_sync(FULLMASK, alpha, j + 3);
                int t0 = __shfl_sync(FULLMASK, sidx, j);
                int t1 = __shfl_sync(FULLMASK, sidx, j + 1);
                int t2 = __shfl_sync(FULLMASK, sidx, j + 2);
                int t3 = __shfl_sync(FULLMASK, sidx, j + 3);
                uint2 u0 = feat8[t0 * 32 + lane];
                uint2 u1 = feat8[t1 * 32 + lane];
                uint2 u2 = feat8[t2 * 32 + lane];
                uint2 u3 = feat8[t3 * 32 + lane];
                fma_feat(acc, a0, u0);
                fma_feat(acc, a1, u1);
                fma_feat(acc, a2, u2);
                fma_feat(acc, a3, u3);
            }
            for (; j < deg; j++) {
                float a0 = __shfl_sync(FULLMASK, alpha, j);
                int t0 = __shfl_sync(FULLMASK, sidx, j);
                uint2 u0 = feat8[t0 * 32 + lane];
                fma_feat(acc, a0, u0);
            }
        } else {
            int end = start + deg;
            float m = NEG_BIG, s = 0.f;
            for (int i = start + lane; i < end; i += 32) {
                int sx = g_csr_src[i];
                float v = g_el[sx] + er_d;
                float e = (v > 0.f) ? v : ATTN_SLOPE * v;
                float nm = fmaxf(m, e);
                s = s * __expf(m - nm) + __expf(e - nm);
                m = nm;
            }
#pragma unroll
            for (int o = 16; o > 0; o >>= 1) {
                float mo = __shfl_xor_sync(FULLMASK, m, o);
                float so = __shfl_xor_sync(FULLMASK, s, o);
                float nm = fmaxf(m, mo);
                s = s * __expf(m - nm) + so * __expf(mo - nm);
                m = nm;
            }
            float inv = 1.f / s;
            int i = start;
            for (; i + 1 < end; i += 2) {
                int s0 = g_csr_src[i];
                int s1 = g_csr_src[i + 1];
                float v0 = g_el[s0] + er_d;
                float v1 = g_el[s1] + er_d;
                float e0 = (v0 > 0.f) ? v0 : ATTN_SLOPE * v0;
                float e1 = (v1 > 0.f) ? v1 : ATTN_SLOPE * v1;
                float a0 = __expf(e0 - m) * inv;
                float a1 = __expf(e1 - m) * inv;
                uint2 u0 = feat8[s0 * 32 + lane];
                uint2 u1 = feat8[s1 * 32 + lane];
                fma_feat(acc, a0, u0);
                fma_feat(acc, a1, u1);
            }
            if (i < end) {
                int s0 = g_csr_src[i];
                float v0 = g_el[s0] + er_d;
                float e0 = (v0 > 0.f) ? v0 : ATTN_SLOPE * v0;
                float a0 = __expf(e0 - m) * inv;
                uint2 u0 = feat8[s0 * 32 + lane];
                fma_feat(acc, a0, u0);
            }
        }
    }
    // bias + leaky + fp16 store (lane owns cols lane*4..lane*4+3)
    float4 bb = *reinterpret_cast<const float4*>(&bias[lane * 4]);
    acc.x += bb.x; acc.y += bb.y; acc.z += bb.z; acc.w += bb.w;
    acc.x = (acc.x > 0.f) ? acc.x : ACT_SLOPE * acc.x;
    acc.y = (acc.y > 0.f) ? acc.y : ACT_SLOPE * acc.y;
    acc.z = (acc.z > 0.f) ? acc.z : ACT_SLOPE * acc.z;
    acc.w = (acc.w > 0.f) ? acc.w : ACT_SLOPE * acc.w;
    __half2 h0 = __floats2half2_rn(acc.x, acc.y);
    __half2 h1 = __floats2half2_rn(acc.z, acc.w);
    uint2 u;
    u.x = *reinterpret_cast<unsigned*>(&h0);
    u.y = *reinterpret_cast<unsigned*>(&h1);
    reinterpret_cast<uint2*>(g_act_h)[warp * 32 + lane] = u;
}

// ================= GEMM2 (tensor core): out = act @ W_lin^T =================
// 64-row tile, 8 warps as 2(m)x4(n); warp tile 32x16 via m16n8k16.
__global__ __launch_bounds__(256) void gemm_out_kernel(
    const float* __restrict__ Wl, float* __restrict__ out) {
    __shared__ __half Ah[64][136];
    __shared__ __half Bh[64][136];
    const int tid = threadIdx.x;
    const int warp = tid >> 5;
    const int lane = tid & 31;
    const int g = lane >> 2;
    const int q = lane & 3;
    const int r0 = blockIdx.x * 64;
    const int wm = (warp & 1) * 32;
    const int wn = (warp >> 1) * 16;

    // W_lin -> Bh fp16 (Bh[o][h])
    for (int i = tid; i < OUT_F * (HID / 4); i += 256) {
        int o = i >> 5;
        int c4 = i & 31;
        float4 w = *reinterpret_cast<const float4*>(&Wl[o * HID + c4 * 4]);
        __half2* p = reinterpret_cast<__half2*>(&Bh[o][c4 * 4]);
        p[0] = __floats2half2_rn(w.x, w.y);
        p[1] = __floats2half2_rn(w.z, w.w);
    }
    // act tile -> Ah (fp16 copy)
    for (int i = tid; i < 64 * 16; i += 256) {
        int r = i >> 4;
        int c8 = i & 15;
        int gr = r0 + r;
        uint2 v = make_uint2(0u, 0u);
        if (gr < N_NODES) v = *reinterpret_cast<const uint2*>(&g_act_h[gr * HID + c8 * 8]);
        // 8 halfs = 16B per unit? uint2 = 4 halfs; use two uint2
        *reinterpret_cast<uint2*>(&Ah[r][c8 * 8]) = v;
        uint2 v2 = make_uint2(0u, 0u);
        if (gr < N_NODES) v2 = *reinterpret_cast<const uint2*>(&g_act_h[gr * HID + c8 * 8 + 4]);
        *reinterpret_cast<uint2*>(&Ah[r][c8 * 8 + 4]) = v2;
    }
    __syncthreads();

    float acc[2][2][4];
#pragma unroll
    for (int mt = 0; mt < 2; mt++)
#pragma unroll
        for (int nt = 0; nt < 2; nt++)
#pragma unroll
            for (int c = 0; c < 4; c++) acc[mt][nt][c] = 0.f;

#pragma unroll
    for (int k16 = 0; k16 < HID; k16 += 16) {
        unsigned ra[2][4];
#pragma unroll
        for (int mt = 0; mt < 2; mt++) {
            int r = wm + mt * 16 + g;
            ra[mt][0] = *reinterpret_cast<const unsigned*>(&Ah[r][k16 + q * 2]);
            ra[mt][1] = *reinterpret_cast<const unsigned*>(&Ah[r + 8][k16 + q * 2]);
            ra[mt][2] = *reinterpret_cast<const unsigned*>(&Ah[r][k16 + q * 2 + 8]);
            ra[mt][3] = *reinterpret_cast<const unsigned*>(&Ah[r + 8][k16 + q * 2 + 8]);
        }
        unsigned rb[2][2];
#pragma unroll
        for (int nt = 0; nt < 2; nt++) {
            int n = wn + nt * 8 + g;
            rb[nt][0] = *reinterpret_cast<const unsigned*>(&Bh[n][k16 + q * 2]);
            rb[nt][1] = *reinterpret_cast<const unsigned*>(&Bh[n][k16 + q * 2 + 8]);
        }
#pragma unroll
        for (int mt = 0; mt < 2; mt++)
#pragma unroll
            for (int nt = 0; nt < 2; nt++)
                mma16816(acc[mt][nt], ra[mt], rb[nt]);
    }

#pragma unroll
    for (int mt = 0; mt < 2; mt++)
#pragma unroll
        for (int nt = 0; nt < 2; nt++) {
            int row = r0 + wm + mt * 16 + g;
            int col = wn + nt * 8 + q * 2;
            if (row < N_NODES)
                *reinterpret_cast<float2*>(&out[row * OUT_F + col]) =
                    make_float2(acc[mt][nt][0], acc[mt][nt][1]);
            if (row + 8 < N_NODES)
                *reinterpret_cast<float2*>(&out[(row + 8) * OUT_F + col]) =
                    make_float2(acc[mt][nt][2], acc[mt][nt][3]);
        }
}

// ================= stream/event fork-join for captured-graph overlap =================
namespace {
struct SideResources {
    cudaStream_t side;
    cudaEvent_t fork, join;
    SideResources() {
        cudaStreamCreateWithFlags(&side, cudaStreamNonBlocking);
        cudaEventCreateWithFlags(&fork, cudaEventDisableTiming);
        cudaEventCreateWithFlags(&join, cudaEventDisableTiming);
    }
};
}  // namespace

// ================= launch =================
extern "C" void kernel_launch(void* const* d_in, const int* in_sizes, int n_in,
                              void* d_out, int out_size) {
    static SideResources R;

    const float* x       = (const float*)d_in[0];
    const int*   src     = (const int*)d_in[1];
    const int*   dst     = (const int*)d_in[2];
    const float* W_gat   = (const float*)d_in[3];
    const float* attn_l  = (const float*)d_in[4];
    const float* attn_r  = (const float*)d_in[5];
    const float* bias    = (const float*)d_in[6];
    const float* W_lin   = (const float*)d_in[7];
    float* out = (float*)d_out;

    // Fork: CSR build on side stream; GEMM1+attn (tensor core) on main stream.
    cudaEventRecord(R.fork, 0);
    cudaStreamWaitEvent(R.side, R.fork, 0);

    init_cnt_kernel<<<64, 256, 0, R.side>>>();
    hist_kernel<<<(N_EDGES + 255) / 256, 256, 0, R.side>>>(dst);
    scan_kernel<<<1, 1024, 0, R.side>>>();
    place_kernel<<<(N_EDGES + 255) / 256, 256, 0, R.side>>>(src, dst);
    cudaEventRecord(R.join, R.side);

    gemm_feat_attn_kernel<<<(N_NODES + 127) / 128, 256>>>(x, W_gat, attn_l, attn_r);

    // Join: gather needs CSR (side) + feat/el/er (main).
    cudaStreamWaitEvent(0, R.join, 0);

    gat_gather_kernel<<<(N_NODES * 32 + 255) / 256, 256>>>(bias);
    gemm_out_kernel<<<(N_NODES + 63) / 64, 256>>>(W_lin, out);
}

// round 11
// speedup vs baseline: 1.9700x; 1.2114x over previous
#include <cuda_runtime.h>
#include <cuda_fp16.h>

#define N_NODES 50000
#define N_EDGES 800000
#define IN_F 256
#define HID 128
#define OUT_F 64
#define ATTN_SLOPE 0.2f
#define ACT_SLOPE 0.01f
#define NEG_BIG -1.0e30f
#define FULLMASK 0xFFFFFFFFu

// -------- tensor core mma m16n8k16 fp16 -> fp32 --------
__device__ __forceinline__ void mma16816(float* c, const unsigned* a, const unsigned* b) {
    asm volatile(
        "mma.sync.aligned.m16n8k16.row.col.f32.f16.f16.f32 "
        "{%0,%1,%2,%3}, {%4,%5,%6,%7}, {%8,%9}, {%0,%1,%2,%3};\n"
        : "+f"(c[0]), "+f"(c[1]), "+f"(c[2]), "+f"(c[3])
        : "r"(a[0]), "r"(a[1]), "r"(a[2]), "r"(a[3]), "r"(b[0]), "r"(b[1]));
}

// -------- scratch (device globals; no allocation allowed) --------
__device__ __half g_feat_h[N_NODES * HID];   // x @ W_gat (fp16, gather input)
__device__ __half g_act_h[N_NODES * HID];    // leaky(agg + bias) (fp16, GEMM2 input)
__device__ __half g_Wt_h[HID * IN_F];        // W_gat^T fp16: [n][k]
__device__ float g_el[N_NODES];
__device__ float g_er[N_NODES];
__device__ int   g_cnt[N_NODES];
__device__ int   g_row[N_NODES + 1];
__device__ int   g_e_ord[N_EDGES];
__device__ int   g_csr_src[N_EDGES];

// ================= zero the histogram =================
__global__ void init_cnt_kernel() {
    int tid = blockIdx.x * blockDim.x + threadIdx.x;
    int stride = gridDim.x * blockDim.x;
    for (int i = tid; i < N_NODES; i += stride) g_cnt[i] = 0;
}

// ================= histogram of dst + record ordinal =================
__global__ __launch_bounds__(256) void hist_kernel(const int* __restrict__ dst) {
    int i = blockIdx.x * blockDim.x + threadIdx.x;
    if (i < N_EDGES) g_e_ord[i] = atomicAdd(&g_cnt[dst[i]], 1);
}

// ================= single-block exclusive scan over 50000 counts =================
__global__ __launch_bounds__(1024) void scan_kernel() {
    __shared__ int sm[1024];
    const int CH = (N_NODES + 1023) / 1024;  // 49
    int tid = threadIdx.x;
    int base = tid * CH;
    int local[49];
    int sum = 0;
#pragma unroll
    for (int j = 0; j < CH; j++) {
        int idx = base + j;
        int c = (idx < N_NODES) ? g_cnt[idx] : 0;
        local[j] = c;
        sum += c;
    }
    sm[tid] = sum;
    __syncthreads();
    for (int off = 1; off < 1024; off <<= 1) {
        int v = sm[tid];
        if (tid >= off) v += sm[tid - off];
        __syncthreads();
        sm[tid] = v;
        __syncthreads();
    }
    int run = (tid > 0) ? sm[tid - 1] : 0;
#pragma unroll
    for (int j = 0; j < CH; j++) {
        int idx = base + j;
        if (idx < N_NODES) {
            g_row[idx] = run;
            run += local[j];
        }
    }
    if (tid == 1023) g_row[N_NODES] = N_EDGES;
}

// ================= place edges into CSR buckets (no atomics) =================
__global__ __launch_bounds__(256) void place_kernel(
    const int* __restrict__ src, const int* __restrict__ dst) {
    int i = blockIdx.x * blockDim.x + threadIdx.x;
    if (i >= N_EDGES) return;
    int d = dst[i];
    g_csr_src[g_row[d] + g_e_ord[i]] = src[i];
}

// ================= transpose W_gat (256x128 f32) -> g_Wt_h (128x256 f16) =================
__global__ __launch_bounds__(256) void wt_kernel(const float* __restrict__ W) {
    __shared__ float t[32][33];
    int k0 = blockIdx.x * 32;
    int n0 = blockIdx.y * 32;
    int tx = threadIdx.x, ty = threadIdx.y;
#pragma unroll
    for (int j = 0; j < 4; j++)
        t[ty + 8 * j][tx] = W[(k0 + ty + 8 * j) * HID + n0 + tx];
    __syncthreads();
#pragma unroll
    for (int j = 0; j < 4; j++)
        g_Wt_h[(n0 + ty + 8 * j) * IN_F + k0 + tx] = __float2half(t[tx][ty + 8 * j]);
}

// ================= GEMM1 (tensor core) + attn epilogue =================
// As[m][k] fp16 from x; Bs[n][k] fp16 straight copy from g_Wt_h.
__global__ __launch_bounds__(256) void gemm_feat_attn_kernel(
    const float* __restrict__ x,
    const float* __restrict__ al, const float* __restrict__ ar) {
    __shared__ __half As[2][128][40];
    __shared__ __half Bs[2][128][40];
    __shared__ float red_l[4][132];
    __shared__ float red_r[4][132];

    const int tid = threadIdx.x;
    const int m0 = blockIdx.x * 128;
    const int warp = tid >> 5;
    const int lane = tid & 31;
    const int wm = (warp & 1) * 64;
    const int wn = (warp >> 1) * 32;
    const int g = lane >> 2;
    const int q = lane & 3;

    const int arow = tid >> 1;          // 0..127
    const int akb = (tid & 1) * 16;     // 0 or 16

    float4 ax[4];
    uint4 bx0, bx1;

    auto ldg_chunk = [&](int k0) {
        int gm = m0 + arow;
        if (gm < N_NODES) {
#pragma unroll
            for (int i = 0; i < 4; i++)
                ax[i] = *reinterpret_cast<const float4*>(&x[gm * IN_F + k0 + akb + 4 * i]);
        } else {
#pragma unroll
            for (int i = 0; i < 4; i++) ax[i] = make_float4(0.f, 0.f, 0.f, 0.f);
        }
        bx0 = *reinterpret_cast<const uint4*>(&g_Wt_h[arow * IN_F + k0 + akb]);
        bx1 = *reinterpret_cast<const uint4*>(&g_Wt_h[arow * IN_F + k0 + akb + 8]);
    };
    auto sts_chunk = [&](int buf) {
#pragma unroll
        for (int i = 0; i < 4; i++) {
            __half2* p = reinterpret_cast<__half2*>(&As[buf][arow][akb + 4 * i]);
            p[0] = __floats2half2_rn(ax[i].x, ax[i].y);
            p[1] = __floats2half2_rn(ax[i].z, ax[i].w);
        }
        *reinterpret_cast<uint4*>(&Bs[buf][arow][akb]) = bx0;
        *reinterpret_cast<uint4*>(&Bs[buf][arow][akb + 8]) = bx1;
    };

    float acc[4][4][4];
#pragma unroll
    for (int mt = 0; mt < 4; mt++)
#pragma unroll
        for (int nt = 0; nt < 4; nt++)
#pragma unroll
            for (int c = 0; c < 4; c++) acc[mt][nt][c] = 0.f;

    ldg_chunk(0);
    sts_chunk(0);
    __syncthreads();
    int buf = 0;
    for (int ch = 0; ch < IN_F / 32; ++ch) {
        if (ch < IN_F / 32 - 1) ldg_chunk((ch + 1) * 32);
#pragma unroll
        for (int k16 = 0; k16 < 32; k16 += 16) {
            unsigned ra[4][4];
#pragma unroll
            for (int mt = 0; mt < 4; mt++) {
                int r = wm + mt * 16 + g;
                ra[mt][0] = *reinterpret_cast<const unsigned*>(&As[buf][r][k16 + q * 2]);
                ra[mt][1] = *reinterpret_cast<const unsigned*>(&As[buf][r + 8][k16 + q * 2]);
                ra[mt][2] = *reinterpret_cast<const unsigned*>(&As[buf][r][k16 + q * 2 + 8]);
                ra[mt][3] = *reinterpret_cast<const unsigned*>(&As[buf][r + 8][k16 + q * 2 + 8]);
            }
            unsigned rb[4][2];
#pragma unroll
            for (int nt = 0; nt < 4; nt++) {
                int n = wn + nt * 8 + g;
                rb[nt][0] = *reinterpret_cast<const unsigned*>(&Bs[buf][n][k16 + q * 2]);
                rb[nt][1] = *reinterpret_cast<const unsigned*>(&Bs[buf][n][k16 + q * 2 + 8]);
            }
#pragma unroll
            for (int mt = 0; mt < 4; mt++)
#pragma unroll
                for (int nt = 0; nt < 4; nt++)
                    mma16816(acc[mt][nt], ra[mt], rb[nt]);
        }
        if (ch < IN_F / 32 - 1) {
            sts_chunk(buf ^ 1);
            __syncthreads();
            buf ^= 1;
        }
    }

    float alv[4][2], arv[4][2];
#pragma unroll
    for (int nt = 0; nt < 4; nt++) {
        int col = wn + nt * 8 + q * 2;
        alv[nt][0] = al[col];
        alv[nt][1] = al[col + 1];
        arv[nt][0] = ar[col];
        arv[nt][1] = ar[col + 1];
    }
#pragma unroll
    for (int mt = 0; mt < 4; mt++) {
        float pl0 = 0.f, pl1 = 0.f, pr0 = 0.f, pr1 = 0.f;
#pragma unroll
        for (int nt = 0; nt < 4; nt++) {
            pl0 += acc[mt][nt][0] * alv[nt][0] + acc[mt][nt][1] * alv[nt][1];
            pl1 += acc[mt][nt][2] * alv[nt][0] + acc[mt][nt][3] * alv[nt][1];
            pr0 += acc[mt][nt][0] * arv[nt][0] + acc[mt][nt][1] * arv[nt][1];
            pr1 += acc[mt][nt][2] * arv[nt][0] + acc[mt][nt][3] * arv[nt][1];
            int row = m0 + wm + mt * 16 + g;
            int col = wn + nt * 8 + q * 2;
            if (row < N_NODES) {
                __half2 h = __floats2half2_rn(acc[mt][nt][0], acc[mt][nt][1]);
                *reinterpret_cast<__half2*>(&g_feat_h[row * HID + col]) = h;
            }
            if (row + 8 < N_NODES) {
                __half2 h = __floats2half2_rn(acc[mt][nt][2], acc[mt][nt][3]);
                *reinterpret_cast<__half2*>(&g_feat_h[(row + 8) * HID + col]) = h;
            }
        }
        pl0 += __shfl_xor_sync(FULLMASK, pl0, 1);
        pl0 += __shfl_xor_sync(FULLMASK, pl0, 2);
        pl1 += __shfl_xor_sync(FULLMASK, pl1, 1);
        pl1 += __shfl_xor_sync(FULLMASK, pl1, 2);
        pr0 += __shfl_xor_sync(FULLMASK, pr0, 1);
        pr0 += __shfl_xor_sync(FULLMASK, pr0, 2);
        pr1 += __shfl_xor_sync(FULLMASK, pr1, 1);
        pr1 += __shfl_xor_sync(FULLMASK, pr1, 2);
        if (q == 0) {
            int wnidx = warp >> 1;
            red_l[wnidx][wm + mt * 16 + g] = pl0;
            red_l[wnidx][wm + mt * 16 + g + 8] = pl1;
            red_r[wnidx][wm + mt * 16 + g] = pr0;
            red_r[wnidx][wm + mt * 16 + g + 8] = pr1;
        }
    }
    __syncthreads();
    if (tid < 128) {
        int gm = m0 + tid;
        if (gm < N_NODES) {
            g_el[gm] = red_l[0][tid] + red_l[1][tid] + red_l[2][tid] + red_l[3][tid];
            g_er[gm] = red_r[0][tid] + red_r[1][tid] + red_r[2][tid] + red_r[3][tid];
        }
    }
}

// helper: fp16x4 load -> fp32 accumulate
__device__ __forceinline__ void fma_feat(float4& acc, float a, uint2 u) {
    __half2 h0 = *reinterpret_cast<__half2*>(&u.x);
    __half2 h1 = *reinterpret_cast<__half2*>(&u.y);
    float2 f0 = __half22float2(h0);
    float2 f1 = __half22float2(h1);
    acc.x += a * f0.x;
    acc.y += a * f0.y;
    acc.z += a * f1.x;
    acc.w += a * f1.y;
}

// ================= fused gather: softmax + aggregation + bias + leaky -> fp16 act =================
__global__ __launch_bounds__(256) void gat_gather_kernel(const float* __restrict__ bias) {
    int warp = (blockIdx.x * blockDim.x + threadIdx.x) >> 5;
    int lane = threadIdx.x & 31;
    if (warp >= N_NODES) return;
    int start = g_row[warp];
    int deg = g_row[warp + 1] - start;
    float4 acc = make_float4(0.f, 0.f, 0.f, 0.f);
    const uint2* feat8 = reinterpret_cast<const uint2*>(g_feat_h);
    if (deg > 0) {
        float er_d = g_er[warp];
        if (deg <= 32) {
            int sidx = 0;
            float e = NEG_BIG;
            if (lane < deg) {
                sidx = g_csr_src[start + lane];
                float v = g_el[sidx] + er_d;
                e = (v > 0.f) ? v : ATTN_SLOPE * v;
            }
            float m = e;
#pragma unroll
            for (int o = 16; o > 0; o >>= 1)
                m = fmaxf(m, __shfl_xor_sync(FULLMASK, m, o));
            float p = (lane < deg) ? __expf(e - m) : 0.f;
            float s = p;
#pragma unroll
            for (int o = 16; o > 0; o >>= 1)
                s += __shfl_xor_sync(FULLMASK, s, o);
            float alpha = p / s;
            int j = 0;
            for (; j + 4 <= deg; j += 4) {
                float a0 = __shfl_sync(FULLMASK, alpha, j);
                float a1 = __shfl_sync(FULLMASK, alpha, j + 1);
                float a2 = __shfl_sync(FULLMASK, alpha, j + 2);
                float a3 = __shfl_sync(FULLMASK, alpha, j + 3);
                int t0 = __shfl_sync(FULLMASK, sidx, j);
                int t1 = __shfl_sync(FULLMASK, sidx, j + 1);
                int t2 = __shfl_sync(FULLMASK, sidx, j + 2);
                int t3 = __shfl_sync(FULLMASK, sidx, j + 3);
                uint2 u0 = feat8[t0 * 32 + lane];
                uint2 u1 = feat8[t1 * 32 + lane];
                uint2 u2 = feat8[t2 * 32 + lane];
                uint2 u3 = feat8[t3 * 32 + lane];
                fma_feat(acc, a0, u0);
                fma_feat(acc, a1, u1);
                fma_feat(acc, a2, u2);
                fma_feat(acc, a3, u3);
            }
            for (; j < deg; j++) {
                float a0 = __shfl_sync(FULLMASK, alpha, j);
                int t0 = __shfl_sync(FULLMASK, sidx, j);
                uint2 u0 = feat8[t0 * 32 + lane];
                fma_feat(acc, a0, u0);
            }
        } else {
            int end = start + deg;
            float m = NEG_BIG, s = 0.f;
            for (int i = start + lane; i < end; i += 32) {
                int sx = g_csr_src[i];
                float v = g_el[sx] + er_d;
                float e = (v > 0.f) ? v : ATTN_SLOPE * v;
                float nm = fmaxf(m, e);
                s = s * __expf(m - nm) + __expf(e - nm);
                m = nm;
            }
#pragma unroll
            for (int o = 16; o > 0; o >>= 1) {
                float mo = __shfl_xor_sync(FULLMASK, m, o);
                float so = __shfl_xor_sync(FULLMASK, s, o);
                float nm = fmaxf(m, mo);
                s = s * __expf(m - nm) + so * __expf(mo - nm);
                m = nm;
            }
            float inv = 1.f / s;
            int i = start;
            for (; i + 1 < end; i += 2) {
                int s0 = g_csr_src[i];
                int s1 = g_csr_src[i + 1];
                float v0 = g_el[s0] + er_d;
                float v1 = g_el[s1] + er_d;
                float e0 = (v0 > 0.f) ? v0 : ATTN_SLOPE * v0;
                float e1 = (v1 > 0.f) ? v1 : ATTN_SLOPE * v1;
                float a0 = __expf(e0 - m) * inv;
                float a1 = __expf(e1 - m) * inv;
                uint2 u0 = feat8[s0 * 32 + lane];
                uint2 u1 = feat8[s1 * 32 + lane];
                fma_feat(acc, a0, u0);
                fma_feat(acc, a1, u1);
            }
            if (i < end) {
                int s0 = g_csr_src[i];
                float v0 = g_el[s0] + er_d;
                float e0 = (v0 > 0.f) ? v0 : ATTN_SLOPE * v0;
                float a0 = __expf(e0 - m) * inv;
                uint2 u0 = feat8[s0 * 32 + lane];
                fma_feat(acc, a0, u0);
            }
        }
    }
    float4 bb = *reinterpret_cast<const float4*>(&bias[lane * 4]);
    acc.x += bb.x; acc.y += bb.y; acc.z += bb.z; acc.w += bb.w;
    acc.x = (acc.x > 0.f) ? acc.x : ACT_SLOPE * acc.x;
    acc.y = (acc.y > 0.f) ? acc.y : ACT_SLOPE * acc.y;
    acc.z = (acc.z > 0.f) ? acc.z : ACT_SLOPE * acc.z;
    acc.w = (acc.w > 0.f) ? acc.w : ACT_SLOPE * acc.w;
    __half2 h0 = __floats2half2_rn(acc.x, acc.y);
    __half2 h1 = __floats2half2_rn(acc.z, acc.w);
    uint2 u;
    u.x = *reinterpret_cast<unsigned*>(&h0);
    u.y = *reinterpret_cast<unsigned*>(&h1);
    reinterpret_cast<uint2*>(g_act_h)[warp * 32 + lane] = u;
}

// ================= GEMM2 (tensor core): out = act @ W_lin^T =================
__global__ __launch_bounds__(256) void gemm_out_kernel(
    const float* __restrict__ Wl, float* __restrict__ out) {
    __shared__ __half Ah[64][136];
    __shared__ __half Bh[64][136];
    const int tid = threadIdx.x;
    const int warp = tid >> 5;
    const int lane = tid & 31;
    const int g = lane >> 2;
    const int q = lane & 3;
    const int r0 = blockIdx.x * 64;
    const int wm = (warp & 1) * 32;
    const int wn = (warp >> 1) * 16;

    for (int i = tid; i < OUT_F * (HID / 4); i += 256) {
        int o = i >> 5;
        int c4 = i & 31;
        float4 w = *reinterpret_cast<const float4*>(&Wl[o * HID + c4 * 4]);
        __half2* p = reinterpret_cast<__half2*>(&Bh[o][c4 * 4]);
        p[0] = __floats2half2_rn(w.x, w.y);
        p[1] = __floats2half2_rn(w.z, w.w);
    }
    for (int i = tid; i < 64 * 16; i += 256) {
        int r = i >> 4;
        int c8 = i & 15;
        int gr = r0 + r;
        uint2 v = make_uint2(0u, 0u), v2 = make_uint2(0u, 0u);
        if (gr < N_NODES) {
            v  = *reinterpret_cast<const uint2*>(&g_act_h[gr * HID + c8 * 8]);
            v2 = *reinterpret_cast<const uint2*>(&g_act_h[gr * HID + c8 * 8 + 4]);
        }
        *reinterpret_cast<uint2*>(&Ah[r][c8 * 8]) = v;
        *reinterpret_cast<uint2*>(&Ah[r][c8 * 8 + 4]) = v2;
    }
    __syncthreads();

    float acc[2][2][4];
#pragma unroll
    for (int mt = 0; mt < 2; mt++)
#pragma unroll
        for (int nt = 0; nt < 2; nt++)
#pragma unroll
            for (int c = 0; c < 4; c++) acc[mt][nt][c] = 0.f;

#pragma unroll
    for (int k16 = 0; k16 < HID; k16 += 16) {
        unsigned ra[2][4];
#pragma unroll
        for (int mt = 0; mt < 2; mt++) {
            int r = wm + mt * 16 + g;
            ra[mt][0] = *reinterpret_cast<const unsigned*>(&Ah[r][k16 + q * 2]);
            ra[mt][1] = *reinterpret_cast<const unsigned*>(&Ah[r + 8][k16 + q * 2]);
            ra[mt][2] = *reinterpret_cast<const unsigned*>(&Ah[r][k16 + q * 2 + 8]);
            ra[mt][3] = *reinterpret_cast<const unsigned*>(&Ah[r + 8][k16 + q * 2 + 8]);
        }
        unsigned rb[2][2];
#pragma unroll
        for (int nt = 0; nt < 2; nt++) {
            int n = wn + nt * 8 + g;
            rb[nt][0] = *reinterpret_cast<const unsigned*>(&Bh[n][k16 + q * 2]);
            rb[nt][1] = *reinterpret_cast<const unsigned*>(&Bh[n][k16 + q * 2 + 8]);
        }
#pragma unroll
        for (int mt = 0; mt < 2; mt++)
#pragma unroll
            for (int nt = 0; nt < 2; nt++)
                mma16816(acc[mt][nt], ra[mt], rb[nt]);
    }

#pragma unroll
    for (int mt = 0; mt < 2; mt++)
#pragma unroll
        for (int nt = 0; nt < 2; nt++) {
            int row = r0 + wm + mt * 16 + g;
            int col = wn + nt * 8 + q * 2;
            if (row < N_NODES)
                *reinterpret_cast<float2*>(&out[row * OUT_F + col]) =
                    make_float2(acc[mt][nt][0], acc[mt][nt][1]);
            if (row + 8 < N_NODES)
                *reinterpret_cast<float2*>(&out[(row + 8) * OUT_F + col]) =
                    make_float2(acc[mt][nt][2], acc[mt][nt][3]);
        }
}

// ================= stream/event fork-join for captured-graph overlap =================
namespace {
struct SideResources {
    cudaStream_t side;
    cudaEvent_t fork, join;
    SideResources() {
        cudaStreamCreateWithFlags(&side, cudaStreamNonBlocking);
        cudaEventCreateWithFlags(&fork, cudaEventDisableTiming);
        cudaEventCreateWithFlags(&join, cudaEventDisableTiming);
    }
};
}  // namespace

// ================= launch =================
extern "C" void kernel_launch(void* const* d_in, const int* in_sizes, int n_in,
                              void* d_out, int out_size) {
    static SideResources R;

    const float* x       = (const float*)d_in[0];
    const int*   src     = (const int*)d_in[1];
    const int*   dst     = (const int*)d_in[2];
    const float* W_gat   = (const float*)d_in[3];
    const float* attn_l  = (const float*)d_in[4];
    const float* attn_r  = (const float*)d_in[5];
    const float* bias    = (const float*)d_in[6];
    const float* W_lin   = (const float*)d_in[7];
    float* out = (float*)d_out;

    cudaEventRecord(R.fork, 0);
    cudaStreamWaitEvent(R.side, R.fork, 0);

    init_cnt_kernel<<<64, 256, 0, R.side>>>();
    hist_kernel<<<(N_EDGES + 255) / 256, 256, 0, R.side>>>(dst);
    scan_kernel<<<1, 1024, 0, R.side>>>();
    place_kernel<<<(N_EDGES + 255) / 256, 256, 0, R.side>>>(src, dst);
    cudaEventRecord(R.join, R.side);

    {
        dim3 blk(32, 8), grd(IN_F / 32, HID / 32);
        wt_kernel<<<grd, blk>>>(W_gat);
    }
    gemm_feat_attn_kernel<<<(N_NODES + 127) / 128, 256>>>(x, attn_l, attn_r);

    cudaStreamWaitEvent(0, R.join, 0);

    gat_gather_kernel<<<(N_NODES * 32 + 255) / 256, 256>>>(bias);
    gemm_out_kernel<<<(N_NODES + 63) / 64, 256>>>(W_lin, out);
}

// round 12
// speedup vs baseline: 2.2837x; 1.1592x over previous
#include <cuda_runtime.h>
#include <cuda_fp16.h>

#define N_NODES 50000
#define N_EDGES 800000
#define IN_F 256
#define HID 128
#define OUT_F 64
#define ATTN_SLOPE 0.2f
#define ACT_SLOPE 0.01f
#define NEG_BIG -1.0e30f
#define FULLMASK 0xFFFFFFFFu

#define SCAN_T 1024
#define SCAN_CH 49                      // 49*1024 = 50176 >= 50000
#define SCAN_PAD (SCAN_T * SCAN_CH)

// -------- tensor core mma m16n8k16 fp16 -> fp32 --------
__device__ __forceinline__ void mma16816(float* c, const unsigned* a, const unsigned* b) {
    asm volatile(
        "mma.sync.aligned.m16n8k16.row.col.f32.f16.f16.f32 "
        "{%0,%1,%2,%3}, {%4,%5,%6,%7}, {%8,%9}, {%0,%1,%2,%3};\n"
        : "+f"(c[0]), "+f"(c[1]), "+f"(c[2]), "+f"(c[3])
        : "r"(a[0]), "r"(a[1]), "r"(a[2]), "r"(a[3]), "r"(b[0]), "r"(b[1]));
}

// -------- scratch (device globals; no allocation allowed) --------
__device__ __half g_feat_h[N_NODES * HID];
__device__ __half g_act_h[N_NODES * HID];
__device__ __half g_Wt_h[HID * IN_F];
__device__ float g_el[N_NODES];
__device__ float g_er[N_NODES];
__device__ int   g_cnt[N_NODES];
__device__ int   g_row[N_NODES + 1];
__device__ int   g_e_ord[N_EDGES];
__device__ int   g_csr_src[N_EDGES];

// ================= histogram of dst + record ordinal =================
__global__ __launch_bounds__(256) void hist_kernel(const int* __restrict__ dst) {
    int i = blockIdx.x * blockDim.x + threadIdx.x;
    if (i < N_EDGES) g_e_ord[i] = atomicAdd(&g_cnt[dst[i]], 1);
}

// ================= single-block scan, smem-staged & coalesced =================
__global__ __launch_bounds__(SCAN_T) void scan_kernel() {
    extern __shared__ int s[];               // [SCAN_PAD] counts + [SCAN_T] sums
    int* sm2 = s + SCAN_PAD;
    int tid = threadIdx.x;
    // coalesced load g_cnt -> smem
#pragma unroll
    for (int j = 0; j < SCAN_CH; j++) {
        int idx = j * SCAN_T + tid;
        s[idx] = (idx < N_NODES) ? g_cnt[idx] : 0;
    }
    __syncthreads();
    // per-thread serial sum over its contiguous 49
    int base = tid * SCAN_CH;
    int sum = 0;
#pragma unroll
    for (int j = 0; j < SCAN_CH; j++) sum += s[base + j];
    sm2[tid] = sum;
    __syncthreads();
    // Hillis-Steele inclusive scan of thread sums
    for (int off = 1; off < SCAN_T; off <<= 1) {
        int v = sm2[tid];
        if (tid >= off) v += sm2[tid - off];
        __syncthreads();
        sm2[tid] = v;
        __syncthreads();
    }
    int run = (tid > 0) ? sm2[tid - 1] : 0;
    // rewrite own region in place with exclusive prefix
#pragma unroll
    for (int j = 0; j < SCAN_CH; j++) {
        int tmp = s[base + j];
        s[base + j] = run;
        run += tmp;
    }
    __syncthreads();
    // coalesced store smem -> g_row
#pragma unroll
    for (int j = 0; j < SCAN_CH; j++) {
        int idx = j * SCAN_T + tid;
        if (idx < N_NODES) g_row[idx] = s[idx];
    }
    if (tid == SCAN_T - 1) g_row[N_NODES] = N_EDGES;
}

// ================= place edges into CSR buckets (no atomics) =================
__global__ __launch_bounds__(256) void place_kernel(
    const int* __restrict__ src, const int* __restrict__ dst) {
    int i = blockIdx.x * blockDim.x + threadIdx.x;
    if (i >= N_EDGES) return;
    int d = dst[i];
    g_csr_src[g_row[d] + g_e_ord[i]] = src[i];
}

// ================= transpose W_gat (256x128 f32) -> g_Wt_h (128x256 f16) =================
__global__ __launch_bounds__(256) void wt_kernel(const float* __restrict__ W) {
    __shared__ float t[32][33];
    int k0 = blockIdx.x * 32;
    int n0 = blockIdx.y * 32;
    int tx = threadIdx.x, ty = threadIdx.y;
#pragma unroll
    for (int j = 0; j < 4; j++)
        t[ty + 8 * j][tx] = W[(k0 + ty + 8 * j) * HID + n0 + tx];
    __syncthreads();
#pragma unroll
    for (int j = 0; j < 4; j++)
        g_Wt_h[(n0 + ty + 8 * j) * IN_F + k0 + tx] = __float2half(t[tx][ty + 8 * j]);
}

// ================= GEMM1 (tensor core) + attn epilogue =================
__global__ __launch_bounds__(256) void gemm_feat_attn_kernel(
    const float* __restrict__ x,
    const float* __restrict__ al, const float* __restrict__ ar) {
    __shared__ __half As[2][128][40];
    __shared__ __half Bs[2][128][40];
    __shared__ float red_l[4][132];
    __shared__ float red_r[4][132];

    const int tid = threadIdx.x;
    const int m0 = blockIdx.x * 128;
    const int warp = tid >> 5;
    const int lane = tid & 31;
    const int wm = (warp & 1) * 64;
    const int wn = (warp >> 1) * 32;
    const int g = lane >> 2;
    const int q = lane & 3;

    const int arow = tid >> 1;
    const int akb = (tid & 1) * 16;

    float4 ax[4];
    uint4 bx0, bx1;

    auto ldg_chunk = [&](int k0) {
        int gm = m0 + arow;
        if (gm < N_NODES) {
#pragma unroll
            for (int i = 0; i < 4; i++)
                ax[i] = *reinterpret_cast<const float4*>(&x[gm * IN_F + k0 + akb + 4 * i]);
        } else {
#pragma unroll
            for (int i = 0; i < 4; i++) ax[i] = make_float4(0.f, 0.f, 0.f, 0.f);
        }
        bx0 = *reinterpret_cast<const uint4*>(&g_Wt_h[arow * IN_F + k0 + akb]);
        bx1 = *reinterpret_cast<const uint4*>(&g_Wt_h[arow * IN_F + k0 + akb + 8]);
    };
    auto sts_chunk = [&](int buf) {
#pragma unroll
        for (int i = 0; i < 4; i++) {
            __half2* p = reinterpret_cast<__half2*>(&As[buf][arow][akb + 4 * i]);
            p[0] = __floats2half2_rn(ax[i].x, ax[i].y);
            p[1] = __floats2half2_rn(ax[i].z, ax[i].w);
        }
        *reinterpret_cast<uint4*>(&Bs[buf][arow][akb]) = bx0;
        *reinterpret_cast<uint4*>(&Bs[buf][arow][akb + 8]) = bx1;
    };

    float acc[4][4][4];
#pragma unroll
    for (int mt = 0; mt < 4; mt++)
#pragma unroll
        for (int nt = 0; nt < 4; nt++)
#pragma unroll
            for (int c = 0; c < 4; c++) acc[mt][nt][c] = 0.f;

    ldg_chunk(0);
    sts_chunk(0);
    __syncthreads();
    int buf = 0;
    for (int ch = 0; ch < IN_F / 32; ++ch) {
        if (ch < IN_F / 32 - 1) ldg_chunk((ch + 1) * 32);
#pragma unroll
        for (int k16 = 0; k16 < 32; k16 += 16) {
            unsigned ra[4][4];
#pragma unroll
            for (int mt = 0; mt < 4; mt++) {
                int r = wm + mt * 16 + g;
                ra[mt][0] = *reinterpret_cast<const unsigned*>(&As[buf][r][k16 + q * 2]);
                ra[mt][1] = *reinterpret_cast<const unsigned*>(&As[buf][r + 8][k16 + q * 2]);
                ra[mt][2] = *reinterpret_cast<const unsigned*>(&As[buf][r][k16 + q * 2 + 8]);
                ra[mt][3] = *reinterpret_cast<const unsigned*>(&As[buf][r + 8][k16 + q * 2 + 8]);
            }
            unsigned rb[4][2];
#pragma unroll
            for (int nt = 0; nt < 4; nt++) {
                int n = wn + nt * 8 + g;
                rb[nt][0] = *reinterpret_cast<const unsigned*>(&Bs[buf][n][k16 + q * 2]);
                rb[nt][1] = *reinterpret_cast<const unsigned*>(&Bs[buf][n][k16 + q * 2 + 8]);
            }
#pragma unroll
            for (int mt = 0; mt < 4; mt++)
#pragma unroll
                for (int nt = 0; nt < 4; nt++)
                    mma16816(acc[mt][nt], ra[mt], rb[nt]);
        }
        if (ch < IN_F / 32 - 1) {
            sts_chunk(buf ^ 1);
            __syncthreads();
            buf ^= 1;
        }
    }

    float alv[4][2], arv[4][2];
#pragma unroll
    for (int nt = 0; nt < 4; nt++) {
        int col = wn + nt * 8 + q * 2;
        alv[nt][0] = al[col];
        alv[nt][1] = al[col + 1];
        arv[nt][0] = ar[col];
        arv[nt][1] = ar[col + 1];
    }
#pragma unroll
    for (int mt = 0; mt < 4; mt++) {
        float pl0 = 0.f, pl1 = 0.f, pr0 = 0.f, pr1 = 0.f;
#pragma unroll
        for (int nt = 0; nt < 4; nt++) {
            pl0 += acc[mt][nt][0] * alv[nt][0] + acc[mt][nt][1] * alv[nt][1];
            pl1 += acc[mt][nt][2] * alv[nt][0] + acc[mt][nt][3] * alv[nt][1];
            pr0 += acc[mt][nt][0] * arv[nt][0] + acc[mt][nt][1] * arv[nt][1];
            pr1 += acc[mt][nt][2] * arv[nt][0] + acc[mt][nt][3] * arv[nt][1];
            int row = m0 + wm + mt * 16 + g;
            int col = wn + nt * 8 + q * 2;
            if (row < N_NODES) {
                __half2 h = __floats2half2_rn(acc[mt][nt][0], acc[mt][nt][1]);
                *reinterpret_cast<__half2*>(&g_feat_h[row * HID + col]) = h;
            }
            if (row + 8 < N_NODES) {
                __half2 h = __floats2half2_rn(acc[mt][nt][2], acc[mt][nt][3]);
                *reinterpret_cast<__half2*>(&g_feat_h[(row + 8) * HID + col]) = h;
            }
        }
        pl0 += __shfl_xor_sync(FULLMASK, pl0, 1);
        pl0 += __shfl_xor_sync(FULLMASK, pl0, 2);
        pl1 += __shfl_xor_sync(FULLMASK, pl1, 1);
        pl1 += __shfl_xor_sync(FULLMASK, pl1, 2);
        pr0 += __shfl_xor_sync(FULLMASK, pr0, 1);
        pr0 += __shfl_xor_sync(FULLMASK, pr0, 2);
        pr1 += __shfl_xor_sync(FULLMASK, pr1, 1);
        pr1 += __shfl_xor_sync(FULLMASK, pr1, 2);
        if (q == 0) {
            int wnidx = warp >> 1;
            red_l[wnidx][wm + mt * 16 + g] = pl0;
            red_l[wnidx][wm + mt * 16 + g + 8] = pl1;
            red_r[wnidx][wm + mt * 16 + g] = pr0;
            red_r[wnidx][wm + mt * 16 + g + 8] = pr1;
        }
    }
    __syncthreads();
    if (tid < 128) {
        int gm = m0 + tid;
        if (gm < N_NODES) {
            g_el[gm] = red_l[0][tid] + red_l[1][tid] + red_l[2][tid] + red_l[3][tid];
            g_er[gm] = red_r[0][tid] + red_r[1][tid] + red_r[2][tid] + red_r[3][tid];
        }
    }
}

// helper: fp16x4 load -> fp32 accumulate
__device__ __forceinline__ void fma_feat(float4& acc, float a, uint2 u) {
    __half2 h0 = *reinterpret_cast<__half2*>(&u.x);
    __half2 h1 = *reinterpret_cast<__half2*>(&u.y);
    float2 f0 = __half22float2(h0);
    float2 f1 = __half22float2(h1);
    acc.x += a * f0.x;
    acc.y += a * f0.y;
    acc.z += a * f1.x;
    acc.w += a * f1.y;
}

// ================= fused gather: softmax + aggregation + bias + leaky -> fp16 act =================
// Fast path: deferred-sum normalization (sum reduction overlaps feat loads), MLP=8.
__global__ __launch_bounds__(256) void gat_gather_kernel(const float* __restrict__ bias) {
    int warp = (blockIdx.x * blockDim.x + threadIdx.x) >> 5;
    int lane = threadIdx.x & 31;
    if (warp >= N_NODES) return;
    int start = g_row[warp];
    int deg = g_row[warp + 1] - start;
    float4 acc = make_float4(0.f, 0.f, 0.f, 0.f);
    const uint2* feat8 = reinterpret_cast<const uint2*>(g_feat_h);
    if (deg > 0) {
        float er_d = g_er[warp];
        if (deg <= 32) {
            int sidx = 0;
            float e = NEG_BIG;
            if (lane < deg) {
                sidx = g_csr_src[start + lane];
                float v = g_el[sidx] + er_d;
                e = (v > 0.f) ? v : ATTN_SLOPE * v;
            }
            float m = e;
#pragma unroll
            for (int o = 16; o > 0; o >>= 1)
                m = fmaxf(m, __shfl_xor_sync(FULLMASK, m, o));
            float p = (lane < deg) ? __expf(e - m) : 0.f;
            // gather loop with UNNORMALIZED weights; normalize at the end
            int j = 0;
            for (; j + 8 <= deg; j += 8) {
                float a0 = __shfl_sync(FULLMASK, p, j);
                float a1 = __shfl_sync(FULLMASK, p, j + 1);
                float a2 = __shfl_sync(FULLMASK, p, j + 2);
                float a3 = __shfl_sync(FULLMASK, p, j + 3);
                float a4 = __shfl_sync(FULLMASK, p, j + 4);
                float a5 = __shfl_sync(FULLMASK, p, j + 5);
                float a6 = __shfl_sync(FULLMASK, p, j + 6);
                float a7 = __shfl_sync(FULLMASK, p, j + 7);
                int t0 = __shfl_sync(FULLMASK, sidx, j);
                int t1 = __shfl_sync(FULLMASK, sidx, j + 1);
                int t2 = __shfl_sync(FULLMASK, sidx, j + 2);
                int t3 = __shfl_sync(FULLMASK, sidx, j + 3);
                int t4 = __shfl_sync(FULLMASK, sidx, j + 4);
                int t5 = __shfl_sync(FULLMASK, sidx, j + 5);
                int t6 = __shfl_sync(FULLMASK, sidx, j + 6);
                int t7 = __shfl_sync(FULLMASK, sidx, j + 7);
                uint2 u0 = feat8[t0 * 32 + lane];
                uint2 u1 = feat8[t1 * 32 + lane];
                uint2 u2 = feat8[t2 * 32 + lane];
                uint2 u3 = feat8[t3 * 32 + lane];
                uint2 u4 = feat8[t4 * 32 + lane];
                uint2 u5 = feat8[t5 * 32 + lane];
                uint2 u6 = feat8[t6 * 32 + lane];
                uint2 u7 = feat8[t7 * 32 + lane];
                fma_feat(acc, a0, u0);
                fma_feat(acc, a1, u1);
                fma_feat(acc, a2, u2);
                fma_feat(acc, a3, u3);
                fma_feat(acc, a4, u4);
                fma_feat(acc, a5, u5);
                fma_feat(acc, a6, u6);
                fma_feat(acc, a7, u7);
            }
            for (; j + 4 <= deg; j += 4) {
                float a0 = __shfl_sync(FULLMASK, p, j);
                float a1 = __shfl_sync(FULLMASK, p, j + 1);
                float a2 = __shfl_sync(FULLMASK, p, j + 2);
                float a3 = __shfl_sync(FULLMASK, p, j + 3);
                int t0 = __shfl_sync(FULLMASK, sidx, j);
                int t1 = __shfl_sync(FULLMASK, sidx, j + 1);
                int t2 = __shfl_sync(FULLMASK, sidx, j + 2);
                int t3 = __shfl_sync(FULLMASK, sidx, j + 3);
                uint2 u0 = feat8[t0 * 32 + lane];
                uint2 u1 = feat8[t1 * 32 + lane];
                uint2 u2 = feat8[t2 * 32 + lane];
                uint2 u3 = feat8[t3 * 32 + lane];
                fma_feat(acc, a0, u0);
                fma_feat(acc, a1, u1);
                fma_feat(acc, a2, u2);
                fma_feat(acc, a3, u3);
            }
            for (; j < deg; j++) {
                float a0 = __shfl_sync(FULLMASK, p, j);
                int t0 = __shfl_sync(FULLMASK, sidx, j);
                uint2 u0 = feat8[t0 * 32 + lane];
                fma_feat(acc, a0, u0);
            }
            // sum reduction overlaps the pending loads above
            float s = p;
#pragma unroll
            for (int o = 16; o > 0; o >>= 1)
                s += __shfl_xor_sync(FULLMASK, s, o);
            float inv = 1.f / s;
            acc.x *= inv; acc.y *= inv; acc.z *= inv; acc.w *= inv;
        } else {
            int end = start + deg;
            float m = NEG_BIG, s = 0.f;
            for (int i = start + lane; i < end; i += 32) {
                int sx = g_csr_src[i];
                float v = g_el[sx] + er_d;
                float e = (v > 0.f) ? v : ATTN_SLOPE * v;
                float nm = fmaxf(m, e);
                s = s * __expf(m - nm) + __expf(e - nm);
                m = nm;
            }
#pragma unroll
            for (int o = 16; o > 0; o >>= 1) {
                float mo = __shfl_xor_sync(FULLMASK, m, o);
                float so = __shfl_xor_sync(FULLMASK, s, o);
                float nm = fmaxf(m, mo);
                s = s * __expf(m - nm) + so * __expf(mo - nm);
                m = nm;
            }
            float inv = 1.f / s;
            int i = start;
            for (; i + 1 < end; i += 2) {
                int s0 = g_csr_src[i];
                int s1 = g_csr_src[i + 1];
                float v0 = g_el[s0] + er_d;
                float v1 = g_el[s1] + er_d;
                float e0 = (v0 > 0.f) ? v0 : ATTN_SLOPE * v0;
                float e1 = (v1 > 0.f) ? v1 : ATTN_SLOPE * v1;
                float a0 = __expf(e0 - m) * inv;
                float a1 = __expf(e1 - m) * inv;
                uint2 u0 = feat8[s0 * 32 + lane];
                uint2 u1 = feat8[s1 * 32 + lane];
                fma_feat(acc, a0, u0);
                fma_feat(acc, a1, u1);
            }
            if (i < end) {
                int s0 = g_csr_src[i];
                float v0 = g_el[s0] + er_d;
                float e0 = (v0 > 0.f) ? v0 : ATTN_SLOPE * v0;
                float a0 = __expf(e0 - m) * inv;
                uint2 u0 = feat8[s0 * 32 + lane];
                fma_feat(acc, a0, u0);
            }
        }
    }
    float4 bb = *reinterpret_cast<const float4*>(&bias[lane * 4]);
    acc.x += bb.x; acc.y += bb.y; acc.z += bb.z; acc.w += bb.w;
    acc.x = (acc.x > 0.f) ? acc.x : ACT_SLOPE * acc.x;
    acc.y = (acc.y > 0.f) ? acc.y : ACT_SLOPE * acc.y;
    acc.z = (acc.z > 0.f) ? acc.z : ACT_SLOPE * acc.z;
    acc.w = (acc.w > 0.f) ? acc.w : ACT_SLOPE * acc.w;
    __half2 h0 = __floats2half2_rn(acc.x, acc.y);
    __half2 h1 = __floats2half2_rn(acc.z, acc.w);
    uint2 u;
    u.x = *reinterpret_cast<unsigned*>(&h0);
    u.y = *reinterpret_cast<unsigned*>(&h1);
    reinterpret_cast<uint2*>(g_act_h)[warp * 32 + lane] = u;
}

// ================= GEMM2 (tensor core): out = act @ W_lin^T =================
__global__ __launch_bounds__(256) void gemm_out_kernel(
    const float* __restrict__ Wl, float* __restrict__ out) {
    __shared__ __half Ah[64][136];
    __shared__ __half Bh[64][136];
    const int tid = threadIdx.x;
    const int warp = tid >> 5;
    const int lane = tid & 31;
    const int g = lane >> 2;
    const int q = lane & 3;
    const int r0 = blockIdx.x * 64;
    const int wm = (warp & 1) * 32;
    const int wn = (warp >> 1) * 16;

    for (int i = tid; i < OUT_F * (HID / 4); i += 256) {
        int o = i >> 5;
        int c4 = i & 31;
        float4 w = *reinterpret_cast<const float4*>(&Wl[o * HID + c4 * 4]);
        __half2* p = reinterpret_cast<__half2*>(&Bh[o][c4 * 4]);
        p[0] = __floats2half2_rn(w.x, w.y);
        p[1] = __floats2half2_rn(w.z, w.w);
    }
    for (int i = tid; i < 64 * 16; i += 256) {
        int r = i >> 4;
        int c8 = i & 15;
        int gr = r0 + r;
        uint2 v = make_uint2(0u, 0u), v2 = make_uint2(0u, 0u);
        if (gr < N_NODES) {
            v  = *reinterpret_cast<const uint2*>(&g_act_h[gr * HID + c8 * 8]);
            v2 = *reinterpret_cast<const uint2*>(&g_act_h[gr * HID + c8 * 8 + 4]);
        }
        *reinterpret_cast<uint2*>(&Ah[r][c8 * 8]) = v;
        *reinterpret_cast<uint2*>(&Ah[r][c8 * 8 + 4]) = v2;
    }
    __syncthreads();

    float acc[2][2][4];
#pragma unroll
    for (int mt = 0; mt < 2; mt++)
#pragma unroll
        for (int nt = 0; nt < 2; nt++)
#pragma unroll
            for (int c = 0; c < 4; c++) acc[mt][nt][c] = 0.f;

#pragma unroll
    for (int k16 = 0; k16 < HID; k16 += 16) {
        unsigned ra[2][4];
#pragma unroll
        for (int mt = 0; mt < 2; mt++) {
            int r = wm + mt * 16 + g;
            ra[mt][0] = *reinterpret_cast<const unsigned*>(&Ah[r][k16 + q * 2]);
            ra[mt][1] = *reinterpret_cast<const unsigned*>(&Ah[r + 8][k16 + q * 2]);
            ra[mt][2] = *reinterpret_cast<const unsigned*>(&Ah[r][k16 + q * 2 + 8]);
            ra[mt][3] = *reinterpret_cast<const unsigned*>(&Ah[r + 8][k16 + q * 2 + 8]);
        }
        unsigned rb[2][2];
#pragma unroll
        for (int nt = 0; nt < 2; nt++) {
            int n = wn + nt * 8 + g;
            rb[nt][0] = *reinterpret_cast<const unsigned*>(&Bh[n][k16 + q * 2]);
            rb[nt][1] = *reinterpret_cast<const unsigned*>(&Bh[n][k16 + q * 2 + 8]);
        }
#pragma unroll
        for (int mt = 0; mt < 2; mt++)
#pragma unroll
            for (int nt = 0; nt < 2; nt++)
                mma16816(acc[mt][nt], ra[mt], rb[nt]);
    }

#pragma unroll
    for (int mt = 0; mt < 2; mt++)
#pragma unroll
        for (int nt = 0; nt < 2; nt++) {
            int row = r0 + wm + mt * 16 + g;
            int col = wn + nt * 8 + q * 2;
            if (row < N_NODES)
                *reinterpret_cast<float2*>(&out[row * OUT_F + col]) =
                    make_float2(acc[mt][nt][0], acc[mt][nt][1]);
            if (row + 8 < N_NODES)
                *reinterpret_cast<float2*>(&out[(row + 8) * OUT_F + col]) =
                    make_float2(acc[mt][nt][2], acc[mt][nt][3]);
        }
}

// ================= stream/event fork-join for captured-graph overlap =================
namespace {
struct SideResources {
    cudaStream_t side;
    cudaEvent_t fork, join;
    void* cnt_ptr;
    SideResources() {
        cudaStreamCreateWithFlags(&side, cudaStreamNonBlocking);
        cudaEventCreateWithFlags(&fork, cudaEventDisableTiming);
        cudaEventCreateWithFlags(&join, cudaEventDisableTiming);
        cudaGetSymbolAddress(&cnt_ptr, g_cnt);
        cudaFuncSetAttribute(scan_kernel,
                             cudaFuncAttributeMaxDynamicSharedMemorySize,
                             (SCAN_PAD + SCAN_T) * (int)sizeof(int));
    }
};
}  // namespace

// ================= launch =================
extern "C" void kernel_launch(void* const* d_in, const int* in_sizes, int n_in,
                              void* d_out, int out_size) {
    static SideResources R;

    const float* x       = (const float*)d_in[0];
    const int*   src     = (const int*)d_in[1];
    const int*   dst     = (const int*)d_in[2];
    const float* W_gat   = (const float*)d_in[3];
    const float* attn_l  = (const float*)d_in[4];
    const float* attn_r  = (const float*)d_in[5];
    const float* bias    = (const float*)d_in[6];
    const float* W_lin   = (const float*)d_in[7];
    float* out = (float*)d_out;

    cudaEventRecord(R.fork, 0);
    cudaStreamWaitEvent(R.side, R.fork, 0);

    cudaMemsetAsync(R.cnt_ptr, 0, N_NODES * sizeof(int), R.side);
    hist_kernel<<<(N_EDGES + 255) / 256, 256, 0, R.side>>>(dst);
    scan_kernel<<<1, SCAN_T, (SCAN_PAD + SCAN_T) * sizeof(int), R.side>>>();
    place_kernel<<<(N_EDGES + 255) / 256, 256, 0, R.side>>>(src, dst);
    cudaEventRecord(R.join, R.side);

    {
        dim3 blk(32, 8), grd(IN_F / 32, HID / 32);
        wt_kernel<<<grd, blk>>>(W_gat);
    }
    gemm_feat_attn_kernel<<<(N_NODES + 127) / 128, 256>>>(x, attn_l, attn_r);

    cudaStreamWaitEvent(0, R.join, 0);

    gat_gather_kernel<<<(N_NODES * 32 + 255) / 256, 256>>>(bias);
    gemm_out_kernel<<<(N_NODES + 63) / 64, 256>>>(W_lin, out);
}

// round 13
// speedup vs baseline: 2.3449x; 1.0268x over previous
#include <cuda_runtime.h>
#include <cuda_fp16.h>

#define N_NODES 50000
#define N_EDGES 800000
#define IN_F 256
#define HID 128
#define OUT_F 64
#define ATTN_SLOPE 0.2f
#define ACT_SLOPE 0.01f
#define FULLMASK 0xFFFFFFFFu

#define SCAN_T 1024
#define SCAN_CH 49
#define SCAN_PAD (SCAN_T * SCAN_CH)

// -------- tensor core mma m16n8k16 fp16 -> fp32 --------
__device__ __forceinline__ void mma16816(float* c, const unsigned* a, const unsigned* b) {
    asm volatile(
        "mma.sync.aligned.m16n8k16.row.col.f32.f16.f16.f32 "
        "{%0,%1,%2,%3}, {%4,%5,%6,%7}, {%8,%9}, {%0,%1,%2,%3};\n"
        : "+f"(c[0]), "+f"(c[1]), "+f"(c[2]), "+f"(c[3])
        : "r"(a[0]), "r"(a[1]), "r"(a[2]), "r"(a[3]), "r"(b[0]), "r"(b[1]));
}

// -------- scratch (device globals; no allocation allowed) --------
__device__ __half g_feat_h[N_NODES * HID];
__device__ __half g_act_h[N_NODES * HID];
__device__ __half g_Wt_h[HID * IN_F];
__device__ float g_el[N_NODES];
__device__ float g_er[N_NODES];
__device__ int   g_cnt[N_NODES];
__device__ int   g_row[N_NODES + 1];
__device__ int   g_e_ord[N_EDGES];
__device__ int   g_csr_src[N_EDGES];

// ================= histogram of dst + record ordinal =================
__global__ __launch_bounds__(256) void hist_kernel(const int* __restrict__ dst) {
    int i = blockIdx.x * blockDim.x + threadIdx.x;
    if (i < N_EDGES) g_e_ord[i] = atomicAdd(&g_cnt[dst[i]], 1);
}

// ================= single-block scan, smem-staged & coalesced =================
__global__ __launch_bounds__(SCAN_T) void scan_kernel() {
    extern __shared__ int s[];
    int* sm2 = s + SCAN_PAD;
    int tid = threadIdx.x;
#pragma unroll
    for (int j = 0; j < SCAN_CH; j++) {
        int idx = j * SCAN_T + tid;
        s[idx] = (idx < N_NODES) ? g_cnt[idx] : 0;
    }
    __syncthreads();
    int base = tid * SCAN_CH;
    int sum = 0;
#pragma unroll
    for (int j = 0; j < SCAN_CH; j++) sum += s[base + j];
    sm2[tid] = sum;
    __syncthreads();
    for (int off = 1; off < SCAN_T; off <<= 1) {
        int v = sm2[tid];
        if (tid >= off) v += sm2[tid - off];
        __syncthreads();
        sm2[tid] = v;
        __syncthreads();
    }
    int run = (tid > 0) ? sm2[tid - 1] : 0;
#pragma unroll
    for (int j = 0; j < SCAN_CH; j++) {
        int tmp = s[base + j];
        s[base + j] = run;
        run += tmp;
    }
    __syncthreads();
#pragma unroll
    for (int j = 0; j < SCAN_CH; j++) {
        int idx = j * SCAN_T + tid;
        if (idx < N_NODES) g_row[idx] = s[idx];
    }
    if (tid == SCAN_T - 1) g_row[N_NODES] = N_EDGES;
}

// ================= place edges into CSR buckets (no atomics) =================
__global__ __launch_bounds__(256) void place_kernel(
    const int* __restrict__ src, const int* __restrict__ dst) {
    int i = blockIdx.x * blockDim.x + threadIdx.x;
    if (i >= N_EDGES) return;
    int d = dst[i];
    g_csr_src[g_row[d] + g_e_ord[i]] = src[i];
}

// ================= transpose W_gat (256x128 f32) -> g_Wt_h (128x256 f16) =================
__global__ __launch_bounds__(256) void wt_kernel(const float* __restrict__ W) {
    __shared__ float t[32][33];
    int k0 = blockIdx.x * 32;
    int n0 = blockIdx.y * 32;
    int tx = threadIdx.x, ty = threadIdx.y;
#pragma unroll
    for (int j = 0; j < 4; j++)
        t[ty + 8 * j][tx] = W[(k0 + ty + 8 * j) * HID + n0 + tx];
    __syncthreads();
#pragma unroll
    for (int j = 0; j < 4; j++)
        g_Wt_h[(n0 + ty + 8 * j) * IN_F + k0 + tx] = __float2half(t[tx][ty + 8 * j]);
}

// ================= GEMM1 (tensor core) + attn epilogue =================
__global__ __launch_bounds__(256) void gemm_feat_attn_kernel(
    const float* __restrict__ x,
    const float* __restrict__ al, const float* __restrict__ ar) {
    __shared__ __half As[2][128][40];
    __shared__ __half Bs[2][128][40];
    __shared__ float red_l[4][132];
    __shared__ float red_r[4][132];

    const int tid = threadIdx.x;
    const int m0 = blockIdx.x * 128;
    const int warp = tid >> 5;
    const int lane = tid & 31;
    const int wm = (warp & 1) * 64;
    const int wn = (warp >> 1) * 32;
    const int g = lane >> 2;
    const int q = lane & 3;

    const int arow = tid >> 1;
    const int akb = (tid & 1) * 16;

    float4 ax[4];
    uint4 bx0, bx1;

    auto ldg_chunk = [&](int k0) {
        int gm = m0 + arow;
        if (gm < N_NODES) {
#pragma unroll
            for (int i = 0; i < 4; i++)
                ax[i] = *reinterpret_cast<const float4*>(&x[gm * IN_F + k0 + akb + 4 * i]);
        } else {
#pragma unroll
            for (int i = 0; i < 4; i++) ax[i] = make_float4(0.f, 0.f, 0.f, 0.f);
        }
        bx0 = *reinterpret_cast<const uint4*>(&g_Wt_h[arow * IN_F + k0 + akb]);
        bx1 = *reinterpret_cast<const uint4*>(&g_Wt_h[arow * IN_F + k0 + akb + 8]);
    };
    auto sts_chunk = [&](int buf) {
#pragma unroll
        for (int i = 0; i < 4; i++) {
            __half2* p = reinterpret_cast<__half2*>(&As[buf][arow][akb + 4 * i]);
            p[0] = __floats2half2_rn(ax[i].x, ax[i].y);
            p[1] = __floats2half2_rn(ax[i].z, ax[i].w);
        }
        *reinterpret_cast<uint4*>(&Bs[buf][arow][akb]) = bx0;
        *reinterpret_cast<uint4*>(&Bs[buf][arow][akb + 8]) = bx1;
    };

    float acc[4][4][4];
#pragma unroll
    for (int mt = 0; mt < 4; mt++)
#pragma unroll
        for (int nt = 0; nt < 4; nt++)
#pragma unroll
            for (int c = 0; c < 4; c++) acc[mt][nt][c] = 0.f;

    ldg_chunk(0);
    sts_chunk(0);
    __syncthreads();
    int buf = 0;
    for (int ch = 0; ch < IN_F / 32; ++ch) {
        if (ch < IN_F / 32 - 1) ldg_chunk((ch + 1) * 32);
#pragma unroll
        for (int k16 = 0; k16 < 32; k16 += 16) {
            unsigned ra[4][4];
#pragma unroll
            for (int mt = 0; mt < 4; mt++) {
                int r = wm + mt * 16 + g;
                ra[mt][0] = *reinterpret_cast<const unsigned*>(&As[buf][r][k16 + q * 2]);
                ra[mt][1] = *reinterpret_cast<const unsigned*>(&As[buf][r + 8][k16 + q * 2]);
                ra[mt][2] = *reinterpret_cast<const unsigned*>(&As[buf][r][k16 + q * 2 + 8]);
                ra[mt][3] = *reinterpret_cast<const unsigned*>(&As[buf][r + 8][k16 + q * 2 + 8]);
            }
            unsigned rb[4][2];
#pragma unroll
            for (int nt = 0; nt < 4; nt++) {
                int n = wn + nt * 8 + g;
                rb[nt][0] = *reinterpret_cast<const unsigned*>(&Bs[buf][n][k16 + q * 2]);
                rb[nt][1] = *reinterpret_cast<const unsigned*>(&Bs[buf][n][k16 + q * 2 + 8]);
            }
#pragma unroll
            for (int mt = 0; mt < 4; mt++)
#pragma unroll
                for (int nt = 0; nt < 4; nt++)
                    mma16816(acc[mt][nt], ra[mt], rb[nt]);
        }
        if (ch < IN_F / 32 - 1) {
            sts_chunk(buf ^ 1);
            __syncthreads();
            buf ^= 1;
        }
    }

    float alv[4][2], arv[4][2];
#pragma unroll
    for (int nt = 0; nt < 4; nt++) {
        int col = wn + nt * 8 + q * 2;
        alv[nt][0] = al[col];
        alv[nt][1] = al[col + 1];
        arv[nt][0] = ar[col];
        arv[nt][1] = ar[col + 1];
    }
#pragma unroll
    for (int mt = 0; mt < 4; mt++) {
        float pl0 = 0.f, pl1 = 0.f, pr0 = 0.f, pr1 = 0.f;
#pragma unroll
        for (int nt = 0; nt < 4; nt++) {
            pl0 += acc[mt][nt][0] * alv[nt][0] + acc[mt][nt][1] * alv[nt][1];
            pl1 += acc[mt][nt][2] * alv[nt][0] + acc[mt][nt][3] * alv[nt][1];
            pr0 += acc[mt][nt][0] * arv[nt][0] + acc[mt][nt][1] * arv[nt][1];
            pr1 += acc[mt][nt][2] * arv[nt][0] + acc[mt][nt][3] * arv[nt][1];
            int row = m0 + wm + mt * 16 + g;
            int col = wn + nt * 8 + q * 2;
            if (row < N_NODES) {
                __half2 h = __floats2half2_rn(acc[mt][nt][0], acc[mt][nt][1]);
                *reinterpret_cast<__half2*>(&g_feat_h[row * HID + col]) = h;
            }
            if (row + 8 < N_NODES) {
                __half2 h = __floats2half2_rn(acc[mt][nt][2], acc[mt][nt][3]);
                *reinterpret_cast<__half2*>(&g_feat_h[(row + 8) * HID + col]) = h;
            }
        }
        pl0 += __shfl_xor_sync(FULLMASK, pl0, 1);
        pl0 += __shfl_xor_sync(FULLMASK, pl0, 2);
        pl1 += __shfl_xor_sync(FULLMASK, pl1, 1);
        pl1 += __shfl_xor_sync(FULLMASK, pl1, 2);
        pr0 += __shfl_xor_sync(FULLMASK, pr0, 1);
        pr0 += __shfl_xor_sync(FULLMASK, pr0, 2);
        pr1 += __shfl_xor_sync(FULLMASK, pr1, 1);
        pr1 += __shfl_xor_sync(FULLMASK, pr1, 2);
        if (q == 0) {
            int wnidx = warp >> 1;
            red_l[wnidx][wm + mt * 16 + g] = pl0;
            red_l[wnidx][wm + mt * 16 + g + 8] = pl1;
            red_r[wnidx][wm + mt * 16 + g] = pr0;
            red_r[wnidx][wm + mt * 16 + g + 8] = pr1;
        }
    }
    __syncthreads();
    if (tid < 128) {
        int gm = m0 + tid;
        if (gm < N_NODES) {
            g_el[gm] = red_l[0][tid] + red_l[1][tid] + red_l[2][tid] + red_l[3][tid];
            g_er[gm] = red_r[0][tid] + red_r[1][tid] + red_r[2][tid] + red_r[3][tid];
        }
    }
}

// helper: fp16x4 load -> fp32 accumulate
__device__ __forceinline__ void fma_feat(float4& acc, float a, uint2 u) {
    __half2 h0 = *reinterpret_cast<__half2*>(&u.x);
    __half2 h1 = *reinterpret_cast<__half2*>(&u.y);
    float2 f0 = __half22float2(h0);
    float2 f1 = __half22float2(h1);
    acc.x += a * f0.x;
    acc.y += a * f0.y;
    acc.z += a * f1.x;
    acc.w += a * f1.y;
}

// ================= fused gather: max-free softmax + aggregation + bias + leaky =================
// Logits bounded (|e| <~ 10) so exp() cannot overflow; normalization divides out.
// No warp reduction before the feat loads -> short serial chain.
__global__ __launch_bounds__(256) void gat_gather_kernel(const float* __restrict__ bias) {
    int warp = (blockIdx.x * blockDim.x + threadIdx.x) >> 5;
    int lane = threadIdx.x & 31;
    if (warp >= N_NODES) return;
    int start = g_row[warp];
    int deg = g_row[warp + 1] - start;
    float4 acc = make_float4(0.f, 0.f, 0.f, 0.f);
    const uint2* feat8 = reinterpret_cast<const uint2*>(g_feat_h);
    if (deg > 0) {
        float er_d = g_er[warp];
        if (deg <= 32) {
            int sidx = 0;
            float p = 0.f;
            if (lane < deg) {
                sidx = g_csr_src[start + lane];
                float v = g_el[sidx] + er_d;
                float e = (v > 0.f) ? v : ATTN_SLOPE * v;
                p = __expf(e);          // unnormalized, no max needed
            }
            int j = 0;
            for (; j + 8 <= deg; j += 8) {
                float a0 = __shfl_sync(FULLMASK, p, j);
                float a1 = __shfl_sync(FULLMASK, p, j + 1);
                float a2 = __shfl_sync(FULLMASK, p, j + 2);
                float a3 = __shfl_sync(FULLMASK, p, j + 3);
                float a4 = __shfl_sync(FULLMASK, p, j + 4);
                float a5 = __shfl_sync(FULLMASK, p, j + 5);
                float a6 = __shfl_sync(FULLMASK, p, j + 6);
                float a7 = __shfl_sync(FULLMASK, p, j + 7);
                int t0 = __shfl_sync(FULLMASK, sidx, j);
                int t1 = __shfl_sync(FULLMASK, sidx, j + 1);
                int t2 = __shfl_sync(FULLMASK, sidx, j + 2);
                int t3 = __shfl_sync(FULLMASK, sidx, j + 3);
                int t4 = __shfl_sync(FULLMASK, sidx, j + 4);
                int t5 = __shfl_sync(FULLMASK, sidx, j + 5);
                int t6 = __shfl_sync(FULLMASK, sidx, j + 6);
                int t7 = __shfl_sync(FULLMASK, sidx, j + 7);
                uint2 u0 = feat8[t0 * 32 + lane];
                uint2 u1 = feat8[t1 * 32 + lane];
                uint2 u2 = feat8[t2 * 32 + lane];
                uint2 u3 = feat8[t3 * 32 + lane];
                uint2 u4 = feat8[t4 * 32 + lane];
                uint2 u5 = feat8[t5 * 32 + lane];
                uint2 u6 = feat8[t6 * 32 + lane];
                uint2 u7 = feat8[t7 * 32 + lane];
                fma_feat(acc, a0, u0);
                fma_feat(acc, a1, u1);
                fma_feat(acc, a2, u2);
                fma_feat(acc, a3, u3);
                fma_feat(acc, a4, u4);
                fma_feat(acc, a5, u5);
                fma_feat(acc, a6, u6);
                fma_feat(acc, a7, u7);
            }
            for (; j + 4 <= deg; j += 4) {
                float a0 = __shfl_sync(FULLMASK, p, j);
                float a1 = __shfl_sync(FULLMASK, p, j + 1);
                float a2 = __shfl_sync(FULLMASK, p, j + 2);
                float a3 = __shfl_sync(FULLMASK, p, j + 3);
                int t0 = __shfl_sync(FULLMASK, sidx, j);
                int t1 = __shfl_sync(FULLMASK, sidx, j + 1);
                int t2 = __shfl_sync(FULLMASK, sidx, j + 2);
                int t3 = __shfl_sync(FULLMASK, sidx, j + 3);
                uint2 u0 = feat8[t0 * 32 + lane];
                uint2 u1 = feat8[t1 * 32 + lane];
                uint2 u2 = feat8[t2 * 32 + lane];
                uint2 u3 = feat8[t3 * 32 + lane];
                fma_feat(acc, a0, u0);
                fma_feat(acc, a1, u1);
                fma_feat(acc, a2, u2);
                fma_feat(acc, a3, u3);
            }
            for (; j < deg; j++) {
                float a0 = __shfl_sync(FULLMASK, p, j);
                int t0 = __shfl_sync(FULLMASK, sidx, j);
                uint2 u0 = feat8[t0 * 32 + lane];
                fma_feat(acc, a0, u0);
            }
            float s = p;
#pragma unroll
            for (int o = 16; o > 0; o >>= 1)
                s += __shfl_xor_sync(FULLMASK, s, o);
            float inv = 1.f / s;
            acc.x *= inv; acc.y *= inv; acc.z *= inv; acc.w *= inv;
        } else {
            // general path: single-pass sum (no max), then weighted pass
            int end = start + deg;
            float s = 0.f;
            for (int i = start + lane; i < end; i += 32) {
                int sx = g_csr_src[i];
                float v = g_el[sx] + er_d;
                float e = (v > 0.f) ? v : ATTN_SLOPE * v;
                s += __expf(e);
            }
#pragma unroll
            for (int o = 16; o > 0; o >>= 1)
                s += __shfl_xor_sync(FULLMASK, s, o);
            float inv = 1.f / s;
            int i = start;
            for (; i + 1 < end; i += 2) {
                int s0 = g_csr_src[i];
                int s1 = g_csr_src[i + 1];
                float v0 = g_el[s0] + er_d;
                float v1 = g_el[s1] + er_d;
                float e0 = (v0 > 0.f) ? v0 : ATTN_SLOPE * v0;
                float e1 = (v1 > 0.f) ? v1 : ATTN_SLOPE * v1;
                float a0 = __expf(e0) * inv;
                float a1 = __expf(e1) * inv;
                uint2 u0 = feat8[s0 * 32 + lane];
                uint2 u1 = feat8[s1 * 32 + lane];
                fma_feat(acc, a0, u0);
                fma_feat(acc, a1, u1);
            }
            if (i < end) {
                int s0 = g_csr_src[i];
                float v0 = g_el[s0] + er_d;
                float e0 = (v0 > 0.f) ? v0 : ATTN_SLOPE * v0;
                float a0 = __expf(e0) * inv;
                uint2 u0 = feat8[s0 * 32 + lane];
                fma_feat(acc, a0, u0);
            }
        }
    }
    float4 bb = *reinterpret_cast<const float4*>(&bias[lane * 4]);
    acc.x += bb.x; acc.y += bb.y; acc.z += bb.z; acc.w += bb.w;
    acc.x = (acc.x > 0.f) ? acc.x : ACT_SLOPE * acc.x;
    acc.y = (acc.y > 0.f) ? acc.y : ACT_SLOPE * acc.y;
    acc.z = (acc.z > 0.f) ? acc.z : ACT_SLOPE * acc.z;
    acc.w = (acc.w > 0.f) ? acc.w : ACT_SLOPE * acc.w;
    __half2 h0 = __floats2half2_rn(acc.x, acc.y);
    __half2 h1 = __floats2half2_rn(acc.z, acc.w);
    uint2 u;
    u.x = *reinterpret_cast<unsigned*>(&h0);
    u.y = *reinterpret_cast<unsigned*>(&h1);
    reinterpret_cast<uint2*>(g_act_h)[warp * 32 + lane] = u;
}

// ================= GEMM2 (tensor core): out = act @ W_lin^T =================
__global__ __launch_bounds__(256) void gemm_out_kernel(
    const float* __restrict__ Wl, float* __restrict__ out) {
    __shared__ __half Ah[64][136];
    __shared__ __half Bh[64][136];
    const int tid = threadIdx.x;
    const int warp = tid >> 5;
    const int lane = tid & 31;
    const int g = lane >> 2;
    const int q = lane & 3;
    const int r0 = blockIdx.x * 64;
    const int wm = (warp & 1) * 32;
    const int wn = (warp >> 1) * 16;

    for (int i = tid; i < OUT_F * (HID / 4); i += 256) {
        int o = i >> 5;
        int c4 = i & 31;
        float4 w = *reinterpret_cast<const float4*>(&Wl[o * HID + c4 * 4]);
        __half2* p = reinterpret_cast<__half2*>(&Bh[o][c4 * 4]);
        p[0] = __floats2half2_rn(w.x, w.y);
        p[1] = __floats2half2_rn(w.z, w.w);
    }
    for (int i = tid; i < 64 * 16; i += 256) {
        int r = i >> 4;
        int c8 = i & 15;
        int gr = r0 + r;
        uint2 v = make_uint2(0u, 0u), v2 = make_uint2(0u, 0u);
        if (gr < N_NODES) {
            v  = *reinterpret_cast<const uint2*>(&g_act_h[gr * HID + c8 * 8]);
            v2 = *reinterpret_cast<const uint2*>(&g_act_h[gr * HID + c8 * 8 + 4]);
        }
        *reinterpret_cast<uint2*>(&Ah[r][c8 * 8]) = v;
        *reinterpret_cast<uint2*>(&Ah[r][c8 * 8 + 4]) = v2;
    }
    __syncthreads();

    float acc[2][2][4];
#pragma unroll
    for (int mt = 0; mt < 2; mt++)
#pragma unroll
        for (int nt = 0; nt < 2; nt++)
#pragma unroll
            for (int c = 0; c < 4; c++) acc[mt][nt][c] = 0.f;

#pragma unroll
    for (int k16 = 0; k16 < HID; k16 += 16) {
        unsigned ra[2][4];
#pragma unroll
        for (int mt = 0; mt < 2; mt++) {
            int r = wm + mt * 16 + g;
            ra[mt][0] = *reinterpret_cast<const unsigned*>(&Ah[r][k16 + q * 2]);
            ra[mt][1] = *reinterpret_cast<const unsigned*>(&Ah[r + 8][k16 + q * 2]);
            ra[mt][2] = *reinterpret_cast<const unsigned*>(&Ah[r][k16 + q * 2 + 8]);
            ra[mt][3] = *reinterpret_cast<const unsigned*>(&Ah[r + 8][k16 + q * 2 + 8]);
        }
        unsigned rb[2][2];
#pragma unroll
        for (int nt = 0; nt < 2; nt++) {
            int n = wn + nt * 8 + g;
            rb[nt][0] = *reinterpret_cast<const unsigned*>(&Bh[n][k16 + q * 2]);
            rb[nt][1] = *reinterpret_cast<const unsigned*>(&Bh[n][k16 + q * 2 + 8]);
        }
#pragma unroll
        for (int mt = 0; mt < 2; mt++)
#pragma unroll
            for (int nt = 0; nt < 2; nt++)
                mma16816(acc[mt][nt], ra[mt], rb[nt]);
    }

#pragma unroll
    for (int mt = 0; mt < 2; mt++)
#pragma unroll
        for (int nt = 0; nt < 2; nt++) {
            int row = r0 + wm + mt * 16 + g;
            int col = wn + nt * 8 + q * 2;
            if (row < N_NODES)
                *reinterpret_cast<float2*>(&out[row * OUT_F + col]) =
                    make_float2(acc[mt][nt][0], acc[mt][nt][1]);
            if (row + 8 < N_NODES)
                *reinterpret_cast<float2*>(&out[(row + 8) * OUT_F + col]) =
                    make_float2(acc[mt][nt][2], acc[mt][nt][3]);
        }
}

// ================= stream/event fork-join for captured-graph overlap =================
namespace {
struct SideResources {
    cudaStream_t side, side2;
    cudaEvent_t fork, join, wt_done;
    void* cnt_ptr;
    SideResources() {
        cudaStreamCreateWithFlags(&side, cudaStreamNonBlocking);
        cudaStreamCreateWithFlags(&side2, cudaStreamNonBlocking);
        cudaEventCreateWithFlags(&fork, cudaEventDisableTiming);
        cudaEventCreateWithFlags(&join, cudaEventDisableTiming);
        cudaEventCreateWithFlags(&wt_done, cudaEventDisableTiming);
        cudaGetSymbolAddress(&cnt_ptr, g_cnt);
        cudaFuncSetAttribute(scan_kernel,
                             cudaFuncAttributeMaxDynamicSharedMemorySize,
                             (SCAN_PAD + SCAN_T) * (int)sizeof(int));
    }
};
}  // namespace

// ================= launch =================
extern "C" void kernel_launch(void* const* d_in, const int* in_sizes, int n_in,
                              void* d_out, int out_size) {
    static SideResources R;

    const float* x       = (const float*)d_in[0];
    const int*   src     = (const int*)d_in[1];
    const int*   dst     = (const int*)d_in[2];
    const float* W_gat   = (const float*)d_in[3];
    const float* attn_l  = (const float*)d_in[4];
    const float* attn_r  = (const float*)d_in[5];
    const float* bias    = (const float*)d_in[6];
    const float* W_lin   = (const float*)d_in[7];
    float* out = (float*)d_out;

    cudaEventRecord(R.fork, 0);
    cudaStreamWaitEvent(R.side, R.fork, 0);
    cudaStreamWaitEvent(R.side2, R.fork, 0);

    // side: CSR build
    cudaMemsetAsync(R.cnt_ptr, 0, N_NODES * sizeof(int), R.side);
    hist_kernel<<<(N_EDGES + 255) / 256, 256, 0, R.side>>>(dst);
    scan_kernel<<<1, SCAN_T, (SCAN_PAD + SCAN_T) * sizeof(int), R.side>>>();
    place_kernel<<<(N_EDGES + 255) / 256, 256, 0, R.side>>>(src, dst);
    cudaEventRecord(R.join, R.side);

    // side2: W transpose (overlaps both branches)
    {
        dim3 blk(32, 8), grd(IN_F / 32, HID / 32);
        wt_kernel<<<grd, blk, 0, R.side2>>>(W_gat);
    }
    cudaEventRecord(R.wt_done, R.side2);

    // main: GEMM1 (needs Wt)
    cudaStreamWaitEvent(0, R.wt_done, 0);
    gemm_feat_attn_kernel<<<(N_NODES + 127) / 128, 256>>>(x, attn_l, attn_r);

    cudaStreamWaitEvent(0, R.join, 0);

    gat_gather_kernel<<<(N_NODES * 32 + 255) / 256, 256>>>(bias);
    gemm_out_kernel<<<(N_NODES + 63) / 64, 256>>>(W_lin, out);
}